// round 4
// baseline (speedup 1.0000x reference)
#include <cuda_runtime.h>
#include <math.h>
#include <stdint.h>

#define NN 50000
#define EE 800000
#define GG 64
#define RR 5
#define BERTD 768
#define HH 128
#define DD 32
#define CCH 2
#define EPSF 1e-5f
#define BETAF 1e-4f

// ---------------- scratch (device globals; no allocation) ----------------
__device__ float g_A[NN * HH];
__device__ float g_B[NN * HH];
__device__ float g_Cacc[NN * HH];
__device__ float g_D[NN * HH];
__device__ float g_P[RR * NN * HH];
__device__ float g_norms[NN];
__device__ float g_normd[NN];
__device__ float g_sum[256];
__device__ float g_sumsq[256];
__device__ float g_scale[256];
__device__ float g_shift[256];
__device__ float g_gsum[GG * HH];
__device__ float g_gcnt[GG];
__device__ float g_xcg[GG * HH];
__device__ float g_xsg[GG * HH];
__device__ float g_h1[GG * 256];
__device__ float g_h2[GG * 256];
__device__ float g_h3[GG * 256];
__device__ float g_xcat[GG * 256];
__device__ int g_perm[GG];

// ---------------- utility kernels ----------------
__global__ void fill0(float4* p, int n4) {
    for (int i = blockIdx.x * blockDim.x + threadIdx.x; i < n4; i += gridDim.x * blockDim.x)
        p[i] = make_float4(0.f, 0.f, 0.f, 0.f);
}

__global__ void deg_kernel(const int* __restrict__ src, const int* __restrict__ dst,
                           float* dout, float* din, int E) {
    int e = blockIdx.x * blockDim.x + threadIdx.x;
    if (e < E) {
        atomicAdd(&dout[src[e]], 1.f);
        atomicAdd(&din[dst[e]], 1.f);
    }
}

__global__ void rsqrt_deg(float* p, int n) {
    int i = blockIdx.x * blockDim.x + threadIdx.x;
    if (i < n) p[i] = rsqrtf(fmaxf(p[i], 1.f));
}

// ---------------- GEMM: C[M,128] = (rowScale*A)[M,Kin] @ W[Kin,128] (+bias)(+addC)(relu) ----
__global__ void __launch_bounds__(256) gemm128(
    const float* __restrict__ A, const float* __restrict__ W,
    const float* __restrict__ bias, const float* __restrict__ addC,
    const float* __restrict__ rowScale, float* __restrict__ out,
    int M, int Kin, int doRelu) {
    __shared__ float As[16][64];
    __shared__ float Ws[16][128];
    int bm = blockIdx.x * 64;
    int tid = threadIdx.x;
    int tx = tid & 15, ty = tid >> 4;
    float acc[4][8];
#pragma unroll
    for (int i = 0; i < 4; i++)
#pragma unroll
        for (int j = 0; j < 8; j++) acc[i][j] = 0.f;

    for (int k0 = 0; k0 < Kin; k0 += 16) {
        // load A tile (64 x 16), transposed into smem [k][m]
        {
            int r = tid >> 2;             // 0..63
            int kk = (tid & 3) << 2;      // 0,4,8,12
            int grow = bm + r;
            float4 v = make_float4(0.f, 0.f, 0.f, 0.f);
            if (grow < M) {
                v = *(const float4*)(A + (size_t)grow * Kin + k0 + kk);
                if (rowScale) {
                    float s = rowScale[grow];
                    v.x *= s; v.y *= s; v.z *= s; v.w *= s;
                }
            }
            As[kk + 0][r] = v.x; As[kk + 1][r] = v.y;
            As[kk + 2][r] = v.z; As[kk + 3][r] = v.w;
        }
        // load W tile (16 x 128)
        {
            int wk = tid >> 4;            // 0..15
            int wc = (tid & 15) << 3;     // 0..120
            const float* wp = W + (size_t)(k0 + wk) * 128 + wc;
            *(float4*)&Ws[wk][wc] = *(const float4*)wp;
            *(float4*)&Ws[wk][wc + 4] = *(const float4*)(wp + 4);
        }
        __syncthreads();
#pragma unroll
        for (int kk2 = 0; kk2 < 16; kk2++) {
            float4 a = *(const float4*)&As[kk2][ty << 2];
            float4 w0 = *(const float4*)&Ws[kk2][tx << 3];
            float4 w1 = *(const float4*)&Ws[kk2][(tx << 3) + 4];
            float av[4] = {a.x, a.y, a.z, a.w};
            float wv[8] = {w0.x, w0.y, w0.z, w0.w, w1.x, w1.y, w1.z, w1.w};
#pragma unroll
            for (int i = 0; i < 4; i++)
#pragma unroll
                for (int j = 0; j < 8; j++) acc[i][j] = fmaf(av[i], wv[j], acc[i][j]);
        }
        __syncthreads();
    }
#pragma unroll
    for (int i = 0; i < 4; i++) {
        int row = bm + (ty << 2) + i;
        if (row >= M) continue;
#pragma unroll
        for (int j0 = 0; j0 < 8; j0 += 4) {
            int col = (tx << 3) + j0;
            float4 o;
            o.x = acc[i][j0 + 0]; o.y = acc[i][j0 + 1];
            o.z = acc[i][j0 + 2]; o.w = acc[i][j0 + 3];
            if (bias) {
                o.x += bias[col]; o.y += bias[col + 1];
                o.z += bias[col + 2]; o.w += bias[col + 3];
            }
            if (addC) {
                float4 c = *(const float4*)(addC + (size_t)row * 128 + col);
                o.x += c.x; o.y += c.y; o.z += c.z; o.w += c.w;
            }
            if (doRelu) {
                o.x = fmaxf(o.x, 0.f); o.y = fmaxf(o.y, 0.f);
                o.z = fmaxf(o.z, 0.f); o.w = fmaxf(o.w, 0.f);
            }
            *(float4*)(out + (size_t)row * 128 + col) = o;
        }
    }
}

// ---------------- BatchNorm (big, over M rows, K<=256 cols) ----------------
__global__ void bn_stats(const float* __restrict__ X, int M, int K,
                         float* sum, float* sumsq) {
    int j = threadIdx.x;  // K threads per block
    float s = 0.f, s2 = 0.f;
    for (int m = blockIdx.x; m < M; m += gridDim.x) {
        float v = X[(size_t)m * K + j];
        s += v; s2 += v * v;
    }
    atomicAdd(&sum[j], s);
    atomicAdd(&sumsq[j], s2);
}

__global__ void bn_fin(const float* sum, const float* sumsq, float invM, int K,
                       float* scale, float* shift) {
    int j = threadIdx.x;
    if (j < K) {
        float mean = sum[j] * invM;
        float var = sumsq[j] * invM - mean * mean;
        float sc = rsqrtf(var + EPSF);
        scale[j] = sc;
        shift[j] = BETAF - mean * sc;
    }
}

__global__ void bn_apply(const float* __restrict__ X, float* __restrict__ Y,
                         const float* __restrict__ scale, const float* __restrict__ shift,
                         const float* __restrict__ rowScale, int M, int K) {
    int total = M * (K >> 2);
    for (int i = blockIdx.x * blockDim.x + threadIdx.x; i < total; i += gridDim.x * blockDim.x) {
        int perRow = K >> 2;
        int row = i / perRow;
        int col = (i - row * perRow) << 2;
        float4 x = *(const float4*)(X + (size_t)row * K + col);
        float4 y;
        y.x = x.x * scale[col] + shift[col];
        y.y = x.y * scale[col + 1] + shift[col + 1];
        y.z = x.z * scale[col + 2] + shift[col + 2];
        y.w = x.w * scale[col + 3] + shift[col + 3];
        if (rowScale) {
            float s = rowScale[row];
            y.x *= s; y.y *= s; y.z *= s; y.w *= s;
        }
        *(float4*)(Y + (size_t)row * K + col) = y;
    }
}

// small BN (M=64 rows)
__global__ void bn_small(const float* __restrict__ in, float* __restrict__ out, int M, int K) {
    int j = blockIdx.x * blockDim.x + threadIdx.x;
    if (j >= K) return;
    float s = 0.f, s2 = 0.f;
    for (int m = 0; m < M; m++) {
        float v = in[m * K + j];
        s += v; s2 += v * v;
    }
    float mean = s / M;
    float var = s2 / M - mean * mean;
    float r = rsqrtf(var + EPSF);
    for (int m = 0; m < M; m++)
        out[m * K + j] = (in[m * K + j] - mean) * r + BETAF;
}

// ---------------- edge scatter kernels ----------------
__global__ void scatter_rel(const float* __restrict__ P, const int* __restrict__ src,
                            const int* __restrict__ dst, const int* __restrict__ et,
                            float* __restrict__ acc, int E) {
    int idx = blockIdx.x * blockDim.x + threadIdx.x;
    int e = idx >> 5;
    if (e >= E) return;
    int c = (idx & 31) << 2;
    const float* msg = P + (size_t)et[e] * (NN * HH);
    int s = src[e], d = dst[e];
    float4 v = *(const float4*)(msg + (size_t)s * HH + c);
    float* ap = acc + (size_t)d * HH + c;
    atomicAdd(ap + 0, v.x); atomicAdd(ap + 1, v.y);
    atomicAdd(ap + 2, v.z); atomicAdd(ap + 3, v.w);
}

__global__ void scatter_edges(const float* __restrict__ msg, const int* __restrict__ src,
                              const int* __restrict__ dst, const float* __restrict__ ew,
                              int ewStride, float* __restrict__ acc, int E) {
    int idx = blockIdx.x * blockDim.x + threadIdx.x;
    int e = idx >> 5;
    if (e >= E) return;
    int c = (idx & 31) << 2;
    int s = src[e], d = dst[e];
    float4 v = *(const float4*)(msg + (size_t)s * HH + c);
    if (ew) {
        float w = ew[(size_t)e * ewStride];
        v.x *= w; v.y *= w; v.z *= w; v.w *= w;
    }
    float* ap = acc + (size_t)d * HH + c;
    atomicAdd(ap + 0, v.x); atomicAdd(ap + 1, v.y);
    atomicAdd(ap + 2, v.z); atomicAdd(ap + 3, v.w);
}

// ---------------- attention kernels ----------------
__global__ void node_att_kernel(const float* __restrict__ x, const float* __restrict__ W,
                                const float* __restrict__ b, float* __restrict__ natt, int Nn) {
    __shared__ float Ws[256];
    for (int i = threadIdx.x; i < 256; i += blockDim.x) Ws[i] = W[i];
    __syncthreads();
    int gi = blockIdx.x * blockDim.x + threadIdx.x;
    int n = gi >> 5, lane = threadIdx.x & 31;
    if (n >= Nn) return;
    float4 xv = *(const float4*)(x + (size_t)n * HH + (lane << 2));
    float vv[4] = {xv.x, xv.y, xv.z, xv.w};
    float s0 = 0.f, s1 = 0.f;
#pragma unroll
    for (int t = 0; t < 4; t++) {
        int k = (lane << 2) + t;
        s0 = fmaf(vv[t], Ws[k * 2 + 0], s0);
        s1 = fmaf(vv[t], Ws[k * 2 + 1], s1);
    }
    for (int o = 16; o > 0; o >>= 1) {
        s0 += __shfl_down_sync(0xffffffffu, s0, o);
        s1 += __shfl_down_sync(0xffffffffu, s1, o);
    }
    if (lane == 0) {
        float z0 = s0 + b[0], z1 = s1 + b[1];
        float m = fmaxf(z0, z1);
        float e0 = expf(z0 - m), e1 = expf(z1 - m);
        float inv = 1.f / (e0 + e1);
        natt[(size_t)n * 2 + 0] = e0 * inv;
        natt[(size_t)n * 2 + 1] = e1 * inv;
    }
}

__global__ void edge_att_kernel(const float* __restrict__ x, const int* __restrict__ src,
                                const int* __restrict__ dst, const float* __restrict__ W,
                                const float* __restrict__ b, float* __restrict__ eatt, int E) {
    __shared__ float Ws[512];
    for (int i = threadIdx.x; i < 512; i += blockDim.x) Ws[i] = W[i];
    __syncthreads();
    int gi = blockIdx.x * blockDim.x + threadIdx.x;
    int e = gi >> 5, lane = threadIdx.x & 31;
    if (e >= E) return;
    int s = src[e], d = dst[e];
    float4 xs = *(const float4*)(x + (size_t)s * HH + (lane << 2));
    float4 xd = *(const float4*)(x + (size_t)d * HH + (lane << 2));
    float vs[4] = {xs.x, xs.y, xs.z, xs.w};
    float vd[4] = {xd.x, xd.y, xd.z, xd.w};
    float s0 = 0.f, s1 = 0.f;
#pragma unroll
    for (int t = 0; t < 4; t++) {
        int k = (lane << 2) + t;
        s0 = fmaf(vs[t], Ws[k * 2 + 0], s0);
        s1 = fmaf(vs[t], Ws[k * 2 + 1], s1);
        s0 = fmaf(vd[t], Ws[(128 + k) * 2 + 0], s0);
        s1 = fmaf(vd[t], Ws[(128 + k) * 2 + 1], s1);
    }
    for (int o = 16; o > 0; o >>= 1) {
        s0 += __shfl_down_sync(0xffffffffu, s0, o);
        s1 += __shfl_down_sync(0xffffffffu, s1, o);
    }
    if (lane == 0) {
        float z0 = s0 + b[0], z1 = s1 + b[1];
        float m = fmaxf(z0, z1);
        float e0 = expf(z0 - m), e1 = expf(z1 - m);
        float inv = 1.f / (e0 + e1);
        eatt[(size_t)e * 2 + 0] = e0 * inv;
        eatt[(size_t)e * 2 + 1] = e1 * inv;
    }
}

__global__ void mul_att(const float* __restrict__ A, const float* __restrict__ natt,
                        int comp, float* __restrict__ B, int Nn) {
    int total = Nn * 32;
    for (int idx = blockIdx.x * blockDim.x + threadIdx.x; idx < total; idx += gridDim.x * blockDim.x) {
        int n = idx >> 5;
        int c = (idx & 31) << 2;
        float w = natt[(size_t)n * 2 + comp];
        float4 v = *(const float4*)(A + (size_t)n * HH + c);
        v.x *= w; v.y *= w; v.z *= w; v.w *= w;
        *(float4*)(B + (size_t)n * HH + c) = v;
    }
}

// ---------------- per-graph mean ----------------
__global__ void gcount_kernel(const int* __restrict__ gid, float* gcnt, int Nn) {
    int n = blockIdx.x * blockDim.x + threadIdx.x;
    if (n < Nn) atomicAdd(&gcnt[gid[n]], 1.f);
}

__global__ void graph_acc(const float* __restrict__ x, const int* __restrict__ gid,
                          float* __restrict__ gsum, int Nn) {
    int idx = blockIdx.x * blockDim.x + threadIdx.x;
    int n = idx >> 5;
    if (n >= Nn) return;
    int c = (idx & 31) << 2;
    int g = gid[n];
    float4 v = *(const float4*)(x + (size_t)n * HH + c);
    float* p = &gsum[g * HH + c];
    atomicAdd(p + 0, v.x); atomicAdd(p + 1, v.y);
    atomicAdd(p + 2, v.z); atomicAdd(p + 3, v.w);
}

__global__ void graph_div(const float* gsum, const float* gcnt, float* xg, float* outx, int total) {
    int i = blockIdx.x * blockDim.x + threadIdx.x;
    if (i >= total) return;
    int g = i / HH;
    float v = gsum[i] / fmaxf(gcnt[g], 1.f);
    xg[i] = v;
    outx[i] = v;
}

// ---------------- small FC / softmax heads ----------------
__global__ void fc_small(const float* __restrict__ A, const float* __restrict__ W,
                         const float* __restrict__ b, float* __restrict__ C,
                         int M, int Kin, int Kout, int doRelu) {
    int i = blockIdx.x * blockDim.x + threadIdx.x;
    if (i >= M * Kout) return;
    int m = i / Kout, j = i - m * Kout;
    float s = b ? b[j] : 0.f;
    for (int k = 0; k < Kin; k++) s = fmaf(A[m * Kin + k], W[k * Kout + j], s);
    C[i] = doRelu ? fmaxf(s, 0.f) : s;
}

__global__ void logsoftmax2(const float* Z, float* out, int M) {
    int i = blockIdx.x * blockDim.x + threadIdx.x;
    if (i >= M) return;
    float z0 = Z[i * 2], z1 = Z[i * 2 + 1];
    float m = fmaxf(z0, z1);
    float l = m + logf(expf(z0 - m) + expf(z1 - m));
    out[i * 2] = z0 - l;
    out[i * 2 + 1] = z1 - l;
}

// ---------------- threefry permutation (replicates jax.random.permutation(key(42), 64)) ----
// JAX partitionable threefry semantics:
//   split(key)[1]      = both output words of threefry(key, x0=0, x1=1) (64-bit iota hi/lo)
//   random_bits 32-bit = bits1 ^ bits2 of threefry(subkey, x0=0, x1=i)
__device__ __forceinline__ void threefry2x32(uint32_t k0, uint32_t k1, uint32_t x0, uint32_t x1,
                                             uint32_t* o0, uint32_t* o1) {
    uint32_t ks[3] = {k0, k1, k0 ^ k1 ^ 0x1BD11BDAu};
    const int r1[4] = {13, 15, 26, 6};
    const int r2[4] = {17, 29, 16, 24};
    x0 += ks[0]; x1 += ks[1];
#pragma unroll
    for (int i = 0; i < 5; i++) {
        const int* rot = (i % 2 == 0) ? r1 : r2;
#pragma unroll
        for (int j = 0; j < 4; j++) {
            x0 += x1;
            x1 = (x1 << rot[j]) | (x1 >> (32 - rot[j]));
            x1 ^= x0;
        }
        x0 += ks[(i + 1) % 3];
        x1 += ks[(i + 2) % 3] + (uint32_t)(i + 1);
    }
    *o0 = x0; *o1 = x1;
}

__global__ void perm_kernel(int* perm) {
    __shared__ uint32_t keys[64];
    int t = threadIdx.x;  // 64 threads
    // partitionable split: subkey = split(key)[1] = threefry((0,42), (0, 1))
    uint32_t sk0, sk1;
    threefry2x32(0u, 42u, 0u, 1u, &sk0, &sk1);
    // partitionable random_bits(subkey, 32, (64,)): counts (hi=0, lo=i), bits = o0 ^ o1
    uint32_t o0, o1;
    threefry2x32(sk0, sk1, 0u, (uint32_t)t, &o0, &o1);
    keys[t] = o0 ^ o1;
    __syncthreads();
    uint32_t ki = keys[t];
    int rank = 0;
    for (int j = 0; j < 64; j++) {
        uint32_t kj = keys[j];
        rank += (kj < ki) || (kj == ki && j < t);
    }
    perm[rank] = t;  // stable sort-by-key order carries original indices
}

__global__ void xcat_kernel(const float* xcg, const float* xsg, const int* perm, float* xcat) {
    int i = blockIdx.x * blockDim.x + threadIdx.x;
    if (i >= GG * 256) return;
    int g = i >> 8, c = i & 255;
    xcat[i] = (c < HH) ? xcg[g * HH + c] : xsg[perm[g] * HH + (c - HH)];
}

// ---------------- launch ----------------
extern "C" void kernel_launch(void* const* d_in, const int* in_sizes, int n_in,
                              void* d_out, int out_size) {
    // resolve inputs by element count (robust to dict-order vs signature-order)
    const float* feat = nullptr;
    const int *src = nullptr, *dst = nullptr, *et = nullptr, *gid = nullptr;
    const float* Wp[27];
    int wi = 0, eseen = 0;
    for (int i = 0; i < n_in; i++) {
        int sz = in_sizes[i];
        if (sz == NN * BERTD) feat = (const float*)d_in[i];
        else if (sz == EE) {
            if (eseen == 0) src = (const int*)d_in[i];
            else if (eseen == 1) dst = (const int*)d_in[i];
            else et = (const int*)d_in[i];
            eseen++;
        } else if (sz == NN) gid = (const int*)d_in[i];
        else if (wi < 27) Wp[wi++] = (const float*)d_in[i];
    }
    const float *W_red = Wp[0], *b_red = Wp[1], *W_rel = Wp[2], *W_self = Wp[3], *b_rel = Wp[4];
    const float *W_conv = Wp[5], *b_conv = Wp[6], *W_eatt = Wp[7], *b_eatt = Wp[8];
    const float *W_natt = Wp[9], *b_natt = Wp[10], *W_cconv = Wp[11], *b_cconv = Wp[12];
    const float *W_sconv = Wp[13], *b_sconv = Wp[14];
    const float *cfc1W = Wp[15], *cfc1b = Wp[16], *cfc2W = Wp[17], *cfc2b = Wp[18];
    const float *sfc1W = Wp[19], *sfc1b = Wp[20], *sfc2W = Wp[21], *sfc2b = Wp[22];
    const float *ccat1W = Wp[23], *ccat1b = Wp[24], *ccat2W = Wp[25], *ccat2b = Wp[26];

    float *A, *B, *Cc, *D, *P, *norms, *normd, *bsum, *bsq, *bsc, *bsh;
    float *gsum, *gcnt, *xcg, *xsg, *h1, *h2, *h3, *xcat;
    int* perm;
    cudaGetSymbolAddress((void**)&A, g_A);
    cudaGetSymbolAddress((void**)&B, g_B);
    cudaGetSymbolAddress((void**)&Cc, g_Cacc);
    cudaGetSymbolAddress((void**)&D, g_D);
    cudaGetSymbolAddress((void**)&P, g_P);
    cudaGetSymbolAddress((void**)&norms, g_norms);
    cudaGetSymbolAddress((void**)&normd, g_normd);
    cudaGetSymbolAddress((void**)&bsum, g_sum);
    cudaGetSymbolAddress((void**)&bsq, g_sumsq);
    cudaGetSymbolAddress((void**)&bsc, g_scale);
    cudaGetSymbolAddress((void**)&bsh, g_shift);
    cudaGetSymbolAddress((void**)&gsum, g_gsum);
    cudaGetSymbolAddress((void**)&gcnt, g_gcnt);
    cudaGetSymbolAddress((void**)&xcg, g_xcg);
    cudaGetSymbolAddress((void**)&xsg, g_xsg);
    cudaGetSymbolAddress((void**)&h1, g_h1);
    cudaGetSymbolAddress((void**)&h2, g_h2);
    cudaGetSymbolAddress((void**)&h3, g_h3);
    cudaGetSymbolAddress((void**)&xcat, g_xcat);
    cudaGetSymbolAddress((void**)&perm, g_perm);

    float* out = (float*)d_out;
    float* out_causal = out;                    // [64,2]
    float* out_spur = out + GG * CCH;           // [64,2]
    float* out_ctx = out + 2 * GG * CCH;        // [64,2]
    float* out_xcg = out + 3 * GG * CCH;        // [64,128]
    float* out_xsg = out_xcg + GG * HH;         // [64,128]
    float* out_natt = out_xsg + GG * HH;        // [N,2]
    float* out_eatt = out_natt + NN * 2;        // [E,2]

    const int NH4 = NN * HH / 4;
    const int gemmGrid = (NN + 63) / 64;
    const int edgeGrid = (EE * 32 + 255) / 256;
    const int nodeWGrid = (NN * 32 + 255) / 256;

    // degrees -> norms (rsqrt(max(dout,1))), normd (rsqrt(max(din,1)))
    fill0<<<64, 256>>>((float4*)norms, NN / 4);
    fill0<<<64, 256>>>((float4*)normd, NN / 4);
    deg_kernel<<<(EE + 255) / 256, 256>>>(src, dst, norms, normd, EE);
    rsqrt_deg<<<(NN + 255) / 256, 256>>>(norms, NN);
    rsqrt_deg<<<(NN + 255) / 256, 256>>>(normd, NN);

    // x = bn(feat @ W_red + b_red)
    gemm128<<<gemmGrid, 256>>>(feat, W_red, b_red, nullptr, nullptr, A, NN, BERTD, 0);
    fill0<<<1, 128>>>((float4*)bsum, 64);
    fill0<<<1, 128>>>((float4*)bsq, 64);
    bn_stats<<<512, 128>>>(A, NN, 128, bsum, bsq);
    bn_fin<<<1, 128>>>(bsum, bsq, 1.f / NN, 128, bsc, bsh);
    bn_apply<<<4096, 256>>>(A, B, bsc, bsh, nullptr, NN, 128);

    // RelGraphConv: per-relation projection + scatter + self loop
    for (int r = 0; r < RR; r++)
        gemm128<<<gemmGrid, 256>>>(B, W_rel + (size_t)r * HH * HH, nullptr, nullptr, nullptr,
                                   P + (size_t)r * NN * HH, NN, HH, 0);
    fill0<<<4096, 256>>>((float4*)Cc, NH4);
    scatter_rel<<<edgeGrid, 256>>>(P, src, dst, et, Cc, EE);
    gemm128<<<gemmGrid, 256>>>(B, W_self, b_rel, Cc, nullptr, A, NN, HH, 1);

    // two GraphConv layers
    for (int i = 0; i < 2; i++) {
        fill0<<<1, 128>>>((float4*)bsum, 64);
        fill0<<<1, 128>>>((float4*)bsq, 64);
        bn_stats<<<512, 128>>>(A, NN, 128, bsum, bsq);
        bn_fin<<<1, 128>>>(bsum, bsq, 1.f / NN, 128, bsc, bsh);
        bn_apply<<<4096, 256>>>(A, B, bsc, bsh, norms, NN, 128);  // * norm_s
        fill0<<<4096, 256>>>((float4*)Cc, NH4);
        scatter_edges<<<edgeGrid, 256>>>(B, src, dst, nullptr, 0, Cc, EE);
        gemm128<<<gemmGrid, 256>>>(Cc, W_conv + (size_t)i * HH * HH, b_conv + i * HH,
                                   nullptr, normd, A, NN, HH, 1);  // * norm_d
    }

    // attentions (from final x in A)
    node_att_kernel<<<nodeWGrid, 256>>>(A, W_natt, b_natt, out_natt, NN);
    edge_att_kernel<<<edgeGrid, 256>>>(A, src, dst, W_eatt, b_eatt, out_eatt, EE);

    // per-graph counts
    fill0<<<1, 16>>>((float4*)gcnt, GG / 4);
    gcount_kernel<<<(NN + 255) / 256, 256>>>(gid, gcnt, NN);

    // causal branch
    mul_att<<<4096, 256>>>(A, out_natt, 0, B, NN);
    fill0<<<1, 128>>>((float4*)bsum, 64);
    fill0<<<1, 128>>>((float4*)bsq, 64);
    bn_stats<<<512, 128>>>(B, NN, 128, bsum, bsq);
    bn_fin<<<1, 128>>>(bsum, bsq, 1.f / NN, 128, bsc, bsh);
    bn_apply<<<4096, 256>>>(B, D, bsc, bsh, norms, NN, 128);
    fill0<<<4096, 256>>>((float4*)Cc, NH4);
    scatter_edges<<<edgeGrid, 256>>>(D, src, dst, out_eatt + 0, 2, Cc, EE);
    gemm128<<<gemmGrid, 256>>>(Cc, W_cconv, b_cconv, nullptr, normd, D, NN, HH, 1);
    fill0<<<8, 256>>>((float4*)gsum, GG * HH / 4);
    graph_acc<<<nodeWGrid, 256>>>(D, gid, gsum, NN);
    graph_div<<<(GG * HH + 255) / 256, 256>>>(gsum, gcnt, xcg, out_xcg, GG * HH);

    // spurious branch
    mul_att<<<4096, 256>>>(A, out_natt, 1, B, NN);
    fill0<<<1, 128>>>((float4*)bsum, 64);
    fill0<<<1, 128>>>((float4*)bsq, 64);
    bn_stats<<<512, 128>>>(B, NN, 128, bsum, bsq);
    bn_fin<<<1, 128>>>(bsum, bsq, 1.f / NN, 128, bsc, bsh);
    bn_apply<<<4096, 256>>>(B, D, bsc, bsh, norms, NN, 128);
    fill0<<<4096, 256>>>((float4*)Cc, NH4);
    scatter_edges<<<edgeGrid, 256>>>(D, src, dst, out_eatt + 1, 2, Cc, EE);
    gemm128<<<gemmGrid, 256>>>(Cc, W_sconv, b_sconv, nullptr, normd, D, NN, HH, 1);
    fill0<<<8, 256>>>((float4*)gsum, GG * HH / 4);
    graph_acc<<<nodeWGrid, 256>>>(D, gid, gsum, NN);
    graph_div<<<(GG * HH + 255) / 256, 256>>>(gsum, gcnt, xsg, out_xsg, GG * HH);

    // causal head
    bn_small<<<1, 128>>>(xcg, h1, GG, 128);
    fc_small<<<(GG * DD + 255) / 256, 256>>>(h1, cfc1W, cfc1b, h2, GG, 128, DD, 1);
    bn_small<<<1, 32>>>(h2, h3, GG, 32);
    fc_small<<<1, 256>>>(h3, cfc2W, cfc2b, out_causal, GG, DD, CCH, 0);

    // spurious head (log_softmax)
    bn_small<<<1, 128>>>(xsg, h1, GG, 128);
    fc_small<<<(GG * DD + 255) / 256, 256>>>(h1, sfc1W, sfc1b, h2, GG, 128, DD, 1);
    bn_small<<<1, 32>>>(h2, h3, GG, 32);
    fc_small<<<1, 256>>>(h3, sfc2W, sfc2b, h2, GG, DD, CCH, 0);
    logsoftmax2<<<1, 64>>>(h2, out_spur, GG);

    // context head (with threefry permutation of xs_g)
    perm_kernel<<<1, 64>>>(perm);
    xcat_kernel<<<(GG * 256 + 255) / 256, 256>>>(xcg, xsg, perm, xcat);
    bn_small<<<1, 256>>>(xcat, h1, GG, 256);
    fc_small<<<(GG * DD + 255) / 256, 256>>>(h1, ccat1W, ccat1b, h2, GG, 256, DD, 1);
    bn_small<<<1, 32>>>(h2, h3, GG, 32);
    fc_small<<<1, 256>>>(h3, ccat2W, ccat2b, out_ctx, GG, DD, CCH, 0);
}

// round 5
// speedup vs baseline: 1.7154x; 1.7154x over previous
#include <cuda_runtime.h>
#include <math.h>
#include <stdint.h>

#define NN 50000
#define EE 800000
#define GG 64
#define RR 5
#define BERTD 768
#define HH 128
#define DD 32
#define CCH 2
#define EPSF 1e-5f
#define BETAF 1e-4f
#define KCAT 768   // 5*128 rel + 128 self

// ---------------- scratch (device globals; no allocation) ----------------
__device__ float g_A[NN * HH];
__device__ float g_B[NN * HH];
__device__ float g_Cacc[NN * HH];
__device__ float g_D[NN * HH];
__device__ float g_S[NN * KCAT];        // rel-aggregated + self concat
__device__ float g_Wcat[KCAT * HH];
__device__ float g_norms[NN];
__device__ float g_normd[NN];
__device__ int g_din[NN];
__device__ int g_dout[NN];
__device__ int g_rowptr[NN + 1];
__device__ int g_cursor[NN];
__device__ int g_eidx[EE];
__device__ float g_sum[256];
__device__ float g_sumsq[256];
__device__ float g_scale[256];
__device__ float g_shift[256];
__device__ float g_gsum[GG * HH];
__device__ float g_gcnt[GG];
__device__ float g_xcg[GG * HH];
__device__ float g_xsg[GG * HH];
__device__ float g_h1[GG * 256];
__device__ float g_h2[GG * 256];
__device__ float g_h3[GG * 256];
__device__ float g_xcat[GG * 256];
__device__ int g_perm[GG];

// ---------------- utility kernels ----------------
__global__ void fill0(float4* p, int n4) {
    for (int i = blockIdx.x * blockDim.x + threadIdx.x; i < n4; i += gridDim.x * blockDim.x)
        p[i] = make_float4(0.f, 0.f, 0.f, 0.f);
}
__global__ void filli0(int* p, int n) {
    for (int i = blockIdx.x * blockDim.x + threadIdx.x; i < n; i += gridDim.x * blockDim.x)
        p[i] = 0;
}

__global__ void degree_int(const int* __restrict__ src, const int* __restrict__ dst,
                           int* dout, int* din, int E) {
    int e = blockIdx.x * blockDim.x + threadIdx.x;
    if (e < E) {
        atomicAdd(&dout[src[e]], 1);
        atomicAdd(&din[dst[e]], 1);
    }
}

__global__ void make_norm(const int* __restrict__ d, float* __restrict__ out, int n) {
    int i = blockIdx.x * blockDim.x + threadIdx.x;
    if (i < n) out[i] = rsqrtf(fmaxf((float)d[i], 1.f));
}

// exclusive prefix sum over n counts -> rowptr[0..n]; single block of 1024
__global__ void scan_rowptr(const int* __restrict__ cnt, int* __restrict__ rowptr, int n) {
    __shared__ int wsum[32];
    __shared__ int carry;
    int tid = threadIdx.x, lane = tid & 31, wid = tid >> 5;
    if (tid == 0) carry = 0;
    __syncthreads();
    for (int base = 0; base < n; base += 1024) {
        int v = (base + tid < n) ? cnt[base + tid] : 0;
        int inc = v;
#pragma unroll
        for (int off = 1; off < 32; off <<= 1) {
            int t = __shfl_up_sync(0xffffffffu, inc, off);
            if (lane >= off) inc += t;
        }
        if (lane == 31) wsum[wid] = inc;
        __syncthreads();
        if (wid == 0) {
            int s = wsum[lane];
            int si = s;
#pragma unroll
            for (int off = 1; off < 32; off <<= 1) {
                int t = __shfl_up_sync(0xffffffffu, si, off);
                if (lane >= off) si += t;
            }
            wsum[lane] = si - s;  // exclusive
        }
        __syncthreads();
        int excl = carry + wsum[wid] + inc - v;
        if (base + tid < n) rowptr[base + tid] = excl;
        __syncthreads();
        if (tid == 1023) carry = excl + v;
        __syncthreads();
    }
    if (threadIdx.x == 0) rowptr[n] = carry;
}

__global__ void build_eidx(const int* __restrict__ dst, const int* __restrict__ rowptr,
                           int* __restrict__ cursor, int* __restrict__ eidx, int E) {
    int e = blockIdx.x * blockDim.x + threadIdx.x;
    if (e < E) {
        int d = dst[e];
        int p = rowptr[d] + atomicAdd(&cursor[d], 1);
        eidx[p] = e;
    }
}

__global__ void build_wcat(const float* __restrict__ Wrel, const float* __restrict__ Wself,
                           float* __restrict__ Wcat) {
    int i = blockIdx.x * blockDim.x + threadIdx.x;
    if (i < RR * HH * HH) Wcat[i] = Wrel[i];
    else if (i < KCAT * HH) Wcat[i] = Wself[i - RR * HH * HH];
}

// ---------------- SGEMM: out[M,128] = A[M,Kin] @ W[Kin,128] (+bias)(relu) ----------------
// 128x128 tile, 8x8 microtile, K-step 16, double-buffered.
__global__ void __launch_bounds__(256) sgemm(
    const float* __restrict__ A, const float* __restrict__ W,
    const float* __restrict__ bias, float* __restrict__ out,
    int M, int Kin, int doRelu) {
    __shared__ float As[2][16][132];
    __shared__ float Ws[2][16][128];
    int tid = threadIdx.x;
    int bm = blockIdx.x * 128;
    int tx = tid & 15, ty = tid >> 4;
    float acc[8][8];
#pragma unroll
    for (int i = 0; i < 8; i++)
#pragma unroll
        for (int j = 0; j < 8; j++) acc[i][j] = 0.f;

    float4 pa[2], pw[2];
    const int T = Kin >> 4;

    // prefetch helpers (manually inlined pattern)
#define LOADA(k0)                                                          \
    {                                                                      \
        _Pragma("unroll") for (int i = 0; i < 2; i++) {                    \
            int idx = tid + i * 256;                                       \
            int row = idx & 127;                                           \
            int kq = (idx >> 7) << 2;                                      \
            int grow = bm + row;                                           \
            float4 v = make_float4(0.f, 0.f, 0.f, 0.f);                    \
            if (grow < M) v = *(const float4*)(A + (size_t)grow * Kin + (k0) + kq); \
            pa[i] = v;                                                     \
        }                                                                  \
    }
#define STOREA(buf)                                                        \
    {                                                                      \
        _Pragma("unroll") for (int i = 0; i < 2; i++) {                    \
            int idx = tid + i * 256;                                       \
            int row = idx & 127;                                           \
            int kq = (idx >> 7) << 2;                                      \
            As[buf][kq + 0][row] = pa[i].x;                                \
            As[buf][kq + 1][row] = pa[i].y;                                \
            As[buf][kq + 2][row] = pa[i].z;                                \
            As[buf][kq + 3][row] = pa[i].w;                                \
        }                                                                  \
    }
#define LOADW(k0)                                                          \
    {                                                                      \
        _Pragma("unroll") for (int i = 0; i < 2; i++) {                    \
            int idx = tid + i * 256;                                       \
            int krow = idx >> 5;                                           \
            int col = (idx & 31) << 2;                                     \
            pw[i] = *(const float4*)(W + (size_t)((k0) + krow) * 128 + col); \
        }                                                                  \
    }
#define STOREW(buf)                                                        \
    {                                                                      \
        _Pragma("unroll") for (int i = 0; i < 2; i++) {                    \
            int idx = tid + i * 256;                                       \
            int krow = idx >> 5;                                           \
            int col = (idx & 31) << 2;                                     \
            *(float4*)&Ws[buf][krow][col] = pw[i];                         \
        }                                                                  \
    }

    LOADA(0); LOADW(0);
    STOREA(0); STOREW(0);
    __syncthreads();

    for (int t = 0; t < T; t++) {
        int cur = t & 1;
        if (t + 1 < T) { LOADA((t + 1) << 4); LOADW((t + 1) << 4); }
#pragma unroll
        for (int k = 0; k < 16; k++) {
            float a[8], b[8];
            *(float4*)&a[0] = *(float4*)&As[cur][k][ty * 8];
            *(float4*)&a[4] = *(float4*)&As[cur][k][ty * 8 + 4];
            *(float4*)&b[0] = *(float4*)&Ws[cur][k][tx * 8];
            *(float4*)&b[4] = *(float4*)&Ws[cur][k][tx * 8 + 4];
#pragma unroll
            for (int i = 0; i < 8; i++)
#pragma unroll
                for (int j = 0; j < 8; j++) acc[i][j] = fmaf(a[i], b[j], acc[i][j]);
        }
        __syncthreads();
        if (t + 1 < T) {
            STOREA(cur ^ 1); STOREW(cur ^ 1);
            __syncthreads();
        }
    }

#pragma unroll
    for (int i = 0; i < 8; i++) {
        int row = bm + ty * 8 + i;
        if (row >= M) continue;
#pragma unroll
        for (int j0 = 0; j0 < 8; j0 += 4) {
            int col = tx * 8 + j0;
            float4 o;
            o.x = acc[i][j0 + 0]; o.y = acc[i][j0 + 1];
            o.z = acc[i][j0 + 2]; o.w = acc[i][j0 + 3];
            if (bias) {
                o.x += bias[col]; o.y += bias[col + 1];
                o.z += bias[col + 2]; o.w += bias[col + 3];
            }
            if (doRelu) {
                o.x = fmaxf(o.x, 0.f); o.y = fmaxf(o.y, 0.f);
                o.z = fmaxf(o.z, 0.f); o.w = fmaxf(o.w, 0.f);
            }
            *(float4*)(out + (size_t)row * 128 + col) = o;
        }
    }
#undef LOADA
#undef STOREA
#undef LOADW
#undef STOREW
}

// ---------------- BatchNorm ----------------
__global__ void bn_stats(const float* __restrict__ X, int M, int K,
                         float* sum, float* sumsq) {
    int j = threadIdx.x;
    float s = 0.f, s2 = 0.f;
    for (int m = blockIdx.x; m < M; m += gridDim.x) {
        float v = X[(size_t)m * K + j];
        s += v; s2 += v * v;
    }
    atomicAdd(&sum[j], s);
    atomicAdd(&sumsq[j], s2);
}

__global__ void bn_fin(const float* sum, const float* sumsq, float invM, int K,
                       float* scale, float* shift) {
    int j = threadIdx.x;
    if (j < K) {
        float mean = sum[j] * invM;
        float var = sumsq[j] * invM - mean * mean;
        float sc = rsqrtf(var + EPSF);
        scale[j] = sc;
        shift[j] = BETAF - mean * sc;
    }
}

__global__ void bn_apply(const float* __restrict__ X, float* __restrict__ Y,
                         const float* __restrict__ scale, const float* __restrict__ shift,
                         const float* __restrict__ rowScale, int M, int K) {
    int total = M * (K >> 2);
    for (int i = blockIdx.x * blockDim.x + threadIdx.x; i < total; i += gridDim.x * blockDim.x) {
        int perRow = K >> 2;
        int row = i / perRow;
        int col = (i - row * perRow) << 2;
        float4 x = *(const float4*)(X + (size_t)row * K + col);
        float4 y;
        y.x = x.x * scale[col] + shift[col];
        y.y = x.y * scale[col + 1] + shift[col + 1];
        y.z = x.z * scale[col + 2] + shift[col + 2];
        y.w = x.w * scale[col + 3] + shift[col + 3];
        if (rowScale) {
            float s = rowScale[row];
            y.x *= s; y.y *= s; y.z *= s; y.w *= s;
        }
        *(float4*)(Y + (size_t)row * K + col) = y;
    }
}

__global__ void bn_small(const float* __restrict__ in, float* __restrict__ out, int M, int K) {
    int j = blockIdx.x * blockDim.x + threadIdx.x;
    if (j >= K) return;
    float s = 0.f, s2 = 0.f;
    for (int m = 0; m < M; m++) {
        float v = in[m * K + j];
        s += v; s2 += v * v;
    }
    float mean = s / M;
    float var = s2 / M - mean * mean;
    float r = rsqrtf(var + EPSF);
    for (int m = 0; m < M; m++)
        out[m * K + j] = (in[m * K + j] - mean) * r + BETAF;
}

// ---------------- CSR aggregation (warp per node, no atomics) ----------------
__global__ void csr_rel_gather(const float* __restrict__ B, const int* __restrict__ eidx,
                               const int* __restrict__ rowptr, const int* __restrict__ src,
                               const int* __restrict__ et, float* __restrict__ S, int Nn) {
    int gw = (blockIdx.x * blockDim.x + threadIdx.x) >> 5;
    if (gw >= Nn) return;
    int c = (threadIdx.x & 31) << 2;
    float4 a0 = make_float4(0, 0, 0, 0), a1 = a0, a2 = a0, a3 = a0, a4 = a0;
    int j0 = rowptr[gw], j1 = rowptr[gw + 1];
    for (int j = j0; j < j1; j++) {
        int e = eidx[j];
        int s = src[e];
        int r = et[e];
        float4 v = *(const float4*)(B + (size_t)s * HH + c);
        if (r == 0)      { a0.x += v.x; a0.y += v.y; a0.z += v.z; a0.w += v.w; }
        else if (r == 1) { a1.x += v.x; a1.y += v.y; a1.z += v.z; a1.w += v.w; }
        else if (r == 2) { a2.x += v.x; a2.y += v.y; a2.z += v.z; a2.w += v.w; }
        else if (r == 3) { a3.x += v.x; a3.y += v.y; a3.z += v.z; a3.w += v.w; }
        else             { a4.x += v.x; a4.y += v.y; a4.z += v.z; a4.w += v.w; }
    }
    float* Sp = S + (size_t)gw * KCAT + c;
    *(float4*)(Sp + 0)   = a0;
    *(float4*)(Sp + 128) = a1;
    *(float4*)(Sp + 256) = a2;
    *(float4*)(Sp + 384) = a3;
    *(float4*)(Sp + 512) = a4;
    *(float4*)(Sp + 640) = *(const float4*)(B + (size_t)gw * HH + c);  // self row
}

__global__ void csr_gather(const float* __restrict__ msg, const int* __restrict__ eidx,
                           const int* __restrict__ rowptr, const int* __restrict__ src,
                           const float* __restrict__ ew, int ewStride,
                           const float* __restrict__ outScale, float* __restrict__ out, int Nn) {
    int gw = (blockIdx.x * blockDim.x + threadIdx.x) >> 5;
    if (gw >= Nn) return;
    int c = (threadIdx.x & 31) << 2;
    float ax = 0.f, ay = 0.f, az = 0.f, aw = 0.f;
    int j0 = rowptr[gw], j1 = rowptr[gw + 1];
    for (int j = j0; j < j1; j++) {
        int e = eidx[j];
        int s = src[e];
        float w = ew ? ew[(size_t)e * ewStride] : 1.f;
        float4 v = *(const float4*)(msg + (size_t)s * HH + c);
        ax = fmaf(v.x, w, ax); ay = fmaf(v.y, w, ay);
        az = fmaf(v.z, w, az); aw = fmaf(v.w, w, aw);
    }
    float sc = outScale ? outScale[gw] : 1.f;
    float4 o = make_float4(ax * sc, ay * sc, az * sc, aw * sc);
    *(float4*)(out + (size_t)gw * HH + c) = o;
}

// ---------------- attention kernels ----------------
__global__ void node_att_kernel(const float* __restrict__ x, const float* __restrict__ W,
                                const float* __restrict__ b, float* __restrict__ natt, int Nn) {
    __shared__ float Ws[256];
    for (int i = threadIdx.x; i < 256; i += blockDim.x) Ws[i] = W[i];
    __syncthreads();
    int gi = blockIdx.x * blockDim.x + threadIdx.x;
    int n = gi >> 5, lane = threadIdx.x & 31;
    if (n >= Nn) return;
    float4 xv = *(const float4*)(x + (size_t)n * HH + (lane << 2));
    float vv[4] = {xv.x, xv.y, xv.z, xv.w};
    float s0 = 0.f, s1 = 0.f;
#pragma unroll
    for (int t = 0; t < 4; t++) {
        int k = (lane << 2) + t;
        s0 = fmaf(vv[t], Ws[k * 2 + 0], s0);
        s1 = fmaf(vv[t], Ws[k * 2 + 1], s1);
    }
    for (int o = 16; o > 0; o >>= 1) {
        s0 += __shfl_down_sync(0xffffffffu, s0, o);
        s1 += __shfl_down_sync(0xffffffffu, s1, o);
    }
    if (lane == 0) {
        float z0 = s0 + b[0], z1 = s1 + b[1];
        float m = fmaxf(z0, z1);
        float e0 = expf(z0 - m), e1 = expf(z1 - m);
        float inv = 1.f / (e0 + e1);
        natt[(size_t)n * 2 + 0] = e0 * inv;
        natt[(size_t)n * 2 + 1] = e1 * inv;
    }
}

__global__ void edge_att_kernel(const float* __restrict__ x, const int* __restrict__ src,
                                const int* __restrict__ dst, const float* __restrict__ W,
                                const float* __restrict__ b, float* __restrict__ eatt, int E) {
    __shared__ float Ws[512];
    for (int i = threadIdx.x; i < 512; i += blockDim.x) Ws[i] = W[i];
    __syncthreads();
    int gi = blockIdx.x * blockDim.x + threadIdx.x;
    int e = gi >> 5, lane = threadIdx.x & 31;
    if (e >= E) return;
    int s = src[e], d = dst[e];
    float4 xs = *(const float4*)(x + (size_t)s * HH + (lane << 2));
    float4 xd = *(const float4*)(x + (size_t)d * HH + (lane << 2));
    float vs[4] = {xs.x, xs.y, xs.z, xs.w};
    float vd[4] = {xd.x, xd.y, xd.z, xd.w};
    float s0 = 0.f, s1 = 0.f;
#pragma unroll
    for (int t = 0; t < 4; t++) {
        int k = (lane << 2) + t;
        s0 = fmaf(vs[t], Ws[k * 2 + 0], s0);
        s1 = fmaf(vs[t], Ws[k * 2 + 1], s1);
        s0 = fmaf(vd[t], Ws[(128 + k) * 2 + 0], s0);
        s1 = fmaf(vd[t], Ws[(128 + k) * 2 + 1], s1);
    }
    for (int o = 16; o > 0; o >>= 1) {
        s0 += __shfl_down_sync(0xffffffffu, s0, o);
        s1 += __shfl_down_sync(0xffffffffu, s1, o);
    }
    if (lane == 0) {
        float z0 = s0 + b[0], z1 = s1 + b[1];
        float m = fmaxf(z0, z1);
        float e0 = expf(z0 - m), e1 = expf(z1 - m);
        float inv = 1.f / (e0 + e1);
        eatt[(size_t)e * 2 + 0] = e0 * inv;
        eatt[(size_t)e * 2 + 1] = e1 * inv;
    }
}

__global__ void mul_att(const float* __restrict__ A, const float* __restrict__ natt,
                        int comp, float* __restrict__ B, int Nn) {
    int total = Nn * 32;
    for (int idx = blockIdx.x * blockDim.x + threadIdx.x; idx < total; idx += gridDim.x * blockDim.x) {
        int n = idx >> 5;
        int c = (idx & 31) << 2;
        float w = natt[(size_t)n * 2 + comp];
        float4 v = *(const float4*)(A + (size_t)n * HH + c);
        v.x *= w; v.y *= w; v.z *= w; v.w *= w;
        *(float4*)(B + (size_t)n * HH + c) = v;
    }
}

// ---------------- per-graph mean ----------------
__global__ void gcount_kernel(const int* __restrict__ gid, float* gcnt, int Nn) {
    int n = blockIdx.x * blockDim.x + threadIdx.x;
    if (n < Nn) atomicAdd(&gcnt[gid[n]], 1.f);
}

__global__ void graph_acc(const float* __restrict__ x, const int* __restrict__ gid,
                          float* __restrict__ gsum, int Nn) {
    int idx = blockIdx.x * blockDim.x + threadIdx.x;
    int n = idx >> 5;
    if (n >= Nn) return;
    int c = (idx & 31) << 2;
    int g = gid[n];
    float4 v = *(const float4*)(x + (size_t)n * HH + c);
    float* p = &gsum[g * HH + c];
    atomicAdd(p + 0, v.x); atomicAdd(p + 1, v.y);
    atomicAdd(p + 2, v.z); atomicAdd(p + 3, v.w);
}

__global__ void graph_div(const float* gsum, const float* gcnt, float* xg, float* outx, int total) {
    int i = blockIdx.x * blockDim.x + threadIdx.x;
    if (i >= total) return;
    int g = i / HH;
    float v = gsum[i] / fmaxf(gcnt[g], 1.f);
    xg[i] = v;
    outx[i] = v;
}

// ---------------- small FC / softmax heads ----------------
__global__ void fc_small(const float* __restrict__ A, const float* __restrict__ W,
                         const float* __restrict__ b, float* __restrict__ C,
                         int M, int Kin, int Kout, int doRelu) {
    int i = blockIdx.x * blockDim.x + threadIdx.x;
    if (i >= M * Kout) return;
    int m = i / Kout, j = i - m * Kout;
    float s = b ? b[j] : 0.f;
    for (int k = 0; k < Kin; k++) s = fmaf(A[m * Kin + k], W[k * Kout + j], s);
    C[i] = doRelu ? fmaxf(s, 0.f) : s;
}

__global__ void logsoftmax2(const float* Z, float* out, int M) {
    int i = blockIdx.x * blockDim.x + threadIdx.x;
    if (i >= M) return;
    float z0 = Z[i * 2], z1 = Z[i * 2 + 1];
    float m = fmaxf(z0, z1);
    float l = m + logf(expf(z0 - m) + expf(z1 - m));
    out[i * 2] = z0 - l;
    out[i * 2 + 1] = z1 - l;
}

// ---------------- threefry permutation (JAX partitionable semantics) ----------------
__device__ __forceinline__ void threefry2x32(uint32_t k0, uint32_t k1, uint32_t x0, uint32_t x1,
                                             uint32_t* o0, uint32_t* o1) {
    uint32_t ks[3] = {k0, k1, k0 ^ k1 ^ 0x1BD11BDAu};
    const int r1[4] = {13, 15, 26, 6};
    const int r2[4] = {17, 29, 16, 24};
    x0 += ks[0]; x1 += ks[1];
#pragma unroll
    for (int i = 0; i < 5; i++) {
        const int* rot = (i % 2 == 0) ? r1 : r2;
#pragma unroll
        for (int j = 0; j < 4; j++) {
            x0 += x1;
            x1 = (x1 << rot[j]) | (x1 >> (32 - rot[j]));
            x1 ^= x0;
        }
        x0 += ks[(i + 1) % 3];
        x1 += ks[(i + 2) % 3] + (uint32_t)(i + 1);
    }
    *o0 = x0; *o1 = x1;
}

__global__ void perm_kernel(int* perm) {
    __shared__ uint32_t keys[64];
    int t = threadIdx.x;
    uint32_t sk0, sk1;
    threefry2x32(0u, 42u, 0u, 1u, &sk0, &sk1);
    uint32_t o0, o1;
    threefry2x32(sk0, sk1, 0u, (uint32_t)t, &o0, &o1);
    keys[t] = o0 ^ o1;
    __syncthreads();
    uint32_t ki = keys[t];
    int rank = 0;
    for (int j = 0; j < 64; j++) {
        uint32_t kj = keys[j];
        rank += (kj < ki) || (kj == ki && j < t);
    }
    perm[rank] = t;
}

__global__ void xcat_kernel(const float* xcg, const float* xsg, const int* perm, float* xcat) {
    int i = blockIdx.x * blockDim.x + threadIdx.x;
    if (i >= GG * 256) return;
    int g = i >> 8, c = i & 255;
    xcat[i] = (c < HH) ? xcg[g * HH + c] : xsg[perm[g] * HH + (c - HH)];
}

// ---------------- launch ----------------
extern "C" void kernel_launch(void* const* d_in, const int* in_sizes, int n_in,
                              void* d_out, int out_size) {
    const float* feat = nullptr;
    const int *src = nullptr, *dst = nullptr, *et = nullptr, *gid = nullptr;
    const float* Wp[27];
    int wi = 0, eseen = 0;
    for (int i = 0; i < n_in; i++) {
        int sz = in_sizes[i];
        if (sz == NN * BERTD) feat = (const float*)d_in[i];
        else if (sz == EE) {
            if (eseen == 0) src = (const int*)d_in[i];
            else if (eseen == 1) dst = (const int*)d_in[i];
            else et = (const int*)d_in[i];
            eseen++;
        } else if (sz == NN) gid = (const int*)d_in[i];
        else if (wi < 27) Wp[wi++] = (const float*)d_in[i];
    }
    const float *W_red = Wp[0], *b_red = Wp[1], *W_rel = Wp[2], *W_self = Wp[3], *b_rel = Wp[4];
    const float *W_conv = Wp[5], *b_conv = Wp[6], *W_eatt = Wp[7], *b_eatt = Wp[8];
    const float *W_natt = Wp[9], *b_natt = Wp[10], *W_cconv = Wp[11], *b_cconv = Wp[12];
    const float *W_sconv = Wp[13], *b_sconv = Wp[14];
    const float *cfc1W = Wp[15], *cfc1b = Wp[16], *cfc2W = Wp[17], *cfc2b = Wp[18];
    const float *sfc1W = Wp[19], *sfc1b = Wp[20], *sfc2W = Wp[21], *sfc2b = Wp[22];
    const float *ccat1W = Wp[23], *ccat1b = Wp[24], *ccat2W = Wp[25], *ccat2b = Wp[26];

    float *A, *B, *Cc, *D, *S, *Wcat, *norms, *normd, *bsum, *bsq, *bsc, *bsh;
    float *gsum, *gcnt, *xcg, *xsg, *h1, *h2, *h3, *xcat;
    int *din, *dout, *rowptr, *cursor, *eidx, *perm;
    cudaGetSymbolAddress((void**)&A, g_A);
    cudaGetSymbolAddress((void**)&B, g_B);
    cudaGetSymbolAddress((void**)&Cc, g_Cacc);
    cudaGetSymbolAddress((void**)&D, g_D);
    cudaGetSymbolAddress((void**)&S, g_S);
    cudaGetSymbolAddress((void**)&Wcat, g_Wcat);
    cudaGetSymbolAddress((void**)&norms, g_norms);
    cudaGetSymbolAddress((void**)&normd, g_normd);
    cudaGetSymbolAddress((void**)&din, g_din);
    cudaGetSymbolAddress((void**)&dout, g_dout);
    cudaGetSymbolAddress((void**)&rowptr, g_rowptr);
    cudaGetSymbolAddress((void**)&cursor, g_cursor);
    cudaGetSymbolAddress((void**)&eidx, g_eidx);
    cudaGetSymbolAddress((void**)&bsum, g_sum);
    cudaGetSymbolAddress((void**)&bsq, g_sumsq);
    cudaGetSymbolAddress((void**)&bsc, g_scale);
    cudaGetSymbolAddress((void**)&bsh, g_shift);
    cudaGetSymbolAddress((void**)&gsum, g_gsum);
    cudaGetSymbolAddress((void**)&gcnt, g_gcnt);
    cudaGetSymbolAddress((void**)&xcg, g_xcg);
    cudaGetSymbolAddress((void**)&xsg, g_xsg);
    cudaGetSymbolAddress((void**)&h1, g_h1);
    cudaGetSymbolAddress((void**)&h2, g_h2);
    cudaGetSymbolAddress((void**)&h3, g_h3);
    cudaGetSymbolAddress((void**)&xcat, g_xcat);
    cudaGetSymbolAddress((void**)&perm, g_perm);

    float* out = (float*)d_out;
    float* out_causal = out;
    float* out_spur = out + GG * CCH;
    float* out_ctx = out + 2 * GG * CCH;
    float* out_xcg = out + 3 * GG * CCH;
    float* out_xsg = out_xcg + GG * HH;
    float* out_natt = out_xsg + GG * HH;
    float* out_eatt = out_natt + NN * 2;

    const int gemmGrid = (NN + 127) / 128;
    const int edgeWGrid = (EE * 32 + 255) / 256;
    const int nodeWGrid = (NN * 32 + 255) / 256;
    const int gatherGrid = (NN + 7) / 8;  // warp per node, 8 warps/block

    // ---- CSR build + degree norms ----
    filli0<<<64, 256>>>(din, NN);
    filli0<<<64, 256>>>(dout, NN);
    filli0<<<64, 256>>>(cursor, NN);
    degree_int<<<(EE + 255) / 256, 256>>>(src, dst, dout, din, EE);
    make_norm<<<(NN + 255) / 256, 256>>>(dout, norms, NN);
    make_norm<<<(NN + 255) / 256, 256>>>(din, normd, NN);
    scan_rowptr<<<1, 1024>>>(din, rowptr, NN);
    build_eidx<<<(EE + 255) / 256, 256>>>(dst, rowptr, cursor, eidx, EE);
    build_wcat<<<(KCAT * HH + 255) / 256, 256>>>(W_rel, W_self, Wcat);

    // ---- x = bn(feat @ W_red + b_red) ----
    sgemm<<<gemmGrid, 256>>>(feat, W_red, b_red, A, NN, BERTD, 0);
    fill0<<<1, 128>>>((float4*)bsum, 64);
    fill0<<<1, 128>>>((float4*)bsq, 64);
    bn_stats<<<512, 128>>>(A, NN, 128, bsum, bsq);
    bn_fin<<<1, 128>>>(bsum, bsq, 1.f / NN, 128, bsc, bsh);
    bn_apply<<<4096, 256>>>(A, B, bsc, bsh, nullptr, NN, 128);

    // ---- RelGraphConv (aggregate-first): S = [per-rel sums | self], one K=768 GEMM ----
    csr_rel_gather<<<gatherGrid, 256>>>(B, eidx, rowptr, src, et, S, NN);
    sgemm<<<gemmGrid, 256>>>(S, Wcat, b_rel, A, NN, KCAT, 1);

    // ---- two GraphConv layers ----
    for (int i = 0; i < 2; i++) {
        fill0<<<1, 128>>>((float4*)bsum, 64);
        fill0<<<1, 128>>>((float4*)bsq, 64);
        bn_stats<<<512, 128>>>(A, NN, 128, bsum, bsq);
        bn_fin<<<1, 128>>>(bsum, bsq, 1.f / NN, 128, bsc, bsh);
        bn_apply<<<4096, 256>>>(A, B, bsc, bsh, norms, NN, 128);
        csr_gather<<<gatherGrid, 256>>>(B, eidx, rowptr, src, nullptr, 0, normd, Cc, NN);
        sgemm<<<gemmGrid, 256>>>(Cc, W_conv + (size_t)i * HH * HH, b_conv + i * HH, A, NN, HH, 1);
    }

    // ---- attentions ----
    node_att_kernel<<<nodeWGrid, 256>>>(A, W_natt, b_natt, out_natt, NN);
    edge_att_kernel<<<edgeWGrid, 256>>>(A, src, dst, W_eatt, b_eatt, out_eatt, EE);

    fill0<<<1, 16>>>((float4*)gcnt, GG / 4);
    gcount_kernel<<<(NN + 255) / 256, 256>>>(gid, gcnt, NN);

    // ---- causal branch ----
    mul_att<<<4096, 256>>>(A, out_natt, 0, B, NN);
    fill0<<<1, 128>>>((float4*)bsum, 64);
    fill0<<<1, 128>>>((float4*)bsq, 64);
    bn_stats<<<512, 128>>>(B, NN, 128, bsum, bsq);
    bn_fin<<<1, 128>>>(bsum, bsq, 1.f / NN, 128, bsc, bsh);
    bn_apply<<<4096, 256>>>(B, D, bsc, bsh, norms, NN, 128);
    csr_gather<<<gatherGrid, 256>>>(D, eidx, rowptr, src, out_eatt + 0, 2, normd, Cc, NN);
    sgemm<<<gemmGrid, 256>>>(Cc, W_cconv, b_cconv, D, NN, HH, 1);
    fill0<<<8, 256>>>((float4*)gsum, GG * HH / 4);
    graph_acc<<<nodeWGrid, 256>>>(D, gid, gsum, NN);
    graph_div<<<(GG * HH + 255) / 256, 256>>>(gsum, gcnt, xcg, out_xcg, GG * HH);

    // ---- spurious branch ----
    mul_att<<<4096, 256>>>(A, out_natt, 1, B, NN);
    fill0<<<1, 128>>>((float4*)bsum, 64);
    fill0<<<1, 128>>>((float4*)bsq, 64);
    bn_stats<<<512, 128>>>(B, NN, 128, bsum, bsq);
    bn_fin<<<1, 128>>>(bsum, bsq, 1.f / NN, 128, bsc, bsh);
    bn_apply<<<4096, 256>>>(B, D, bsc, bsh, norms, NN, 128);
    csr_gather<<<gatherGrid, 256>>>(D, eidx, rowptr, src, out_eatt + 1, 2, normd, Cc, NN);
    sgemm<<<gemmGrid, 256>>>(Cc, W_sconv, b_sconv, D, NN, HH, 1);
    fill0<<<8, 256>>>((float4*)gsum, GG * HH / 4);
    graph_acc<<<nodeWGrid, 256>>>(D, gid, gsum, NN);
    graph_div<<<(GG * HH + 255) / 256, 256>>>(gsum, gcnt, xsg, out_xsg, GG * HH);

    // ---- causal head ----
    bn_small<<<1, 128>>>(xcg, h1, GG, 128);
    fc_small<<<(GG * DD + 255) / 256, 256>>>(h1, cfc1W, cfc1b, h2, GG, 128, DD, 1);
    bn_small<<<1, 32>>>(h2, h3, GG, 32);
    fc_small<<<1, 256>>>(h3, cfc2W, cfc2b, out_causal, GG, DD, CCH, 0);

    // ---- spurious head ----
    bn_small<<<1, 128>>>(xsg, h1, GG, 128);
    fc_small<<<(GG * DD + 255) / 256, 256>>>(h1, sfc1W, sfc1b, h2, GG, 128, DD, 1);
    bn_small<<<1, 32>>>(h2, h3, GG, 32);
    fc_small<<<1, 256>>>(h3, sfc2W, sfc2b, h2, GG, DD, CCH, 0);
    logsoftmax2<<<1, 64>>>(h2, out_spur, GG);

    // ---- context head ----
    perm_kernel<<<1, 64>>>(perm);
    xcat_kernel<<<(GG * 256 + 255) / 256, 256>>>(xcg, xsg, perm, xcat);
    bn_small<<<1, 256>>>(xcat, h1, GG, 256);
    fc_small<<<(GG * DD + 255) / 256, 256>>>(h1, ccat1W, ccat1b, h2, GG, 256, DD, 1);
    bn_small<<<1, 32>>>(h2, h3, GG, 32);
    fc_small<<<1, 256>>>(h3, ccat2W, ccat2b, out_ctx, GG, DD, CCH, 0);
}

// round 7
// speedup vs baseline: 2.3294x; 1.3580x over previous
#include <cuda_runtime.h>
#include <cuda_bf16.h>
#include <math.h>
#include <stdint.h>

#define NN 50000
#define EE 800000
#define GG 64
#define RR 5
#define BERTD 768
#define HH 128
#define DD 32
#define CCH 2
#define EPSF 1e-5f
#define BETAF 1e-4f
#define KCAT 768   // 5*128 rel + 128 self

// ---------------- scratch (device globals; no allocation) ----------------
__device__ float g_A[NN * HH];
__device__ float g_B[NN * HH];
__device__ float g_Cacc[NN * HH];
__device__ float g_D[NN * HH];
__device__ float g_S[NN * KCAT];
__device__ float g_Wcat[KCAT * HH];
__device__ float g_norms[NN];
__device__ float g_normd[NN];
__device__ int g_din[NN];
__device__ int g_dout[NN];
__device__ int g_rowptr[NN + 1];
__device__ int g_cursor[NN];
__device__ int g_eidx[EE];
__device__ float g_sum[256];
__device__ float g_sumsq[256];
__device__ float g_scale[256];
__device__ float g_shift[256];
__device__ float g_gsum[GG * HH];
__device__ float g_gcnt[GG];
__device__ float g_xcg[GG * HH];
__device__ float g_xsg[GG * HH];
__device__ float g_h1[GG * 256];
__device__ float g_h2[GG * 256];
__device__ float g_h3[GG * 256];
__device__ float g_xcat[GG * 256];
__device__ int g_perm[GG];

// ---------------- mma.sync helpers ----------------
__device__ __forceinline__ void ldsm_x4(uint32_t* r, uint32_t addr) {
    asm volatile("ldmatrix.sync.aligned.m8n8.x4.shared.b16 {%0,%1,%2,%3}, [%4];"
                 : "=r"(r[0]), "=r"(r[1]), "=r"(r[2]), "=r"(r[3]) : "r"(addr));
}
__device__ __forceinline__ void ldsm_x2t(uint32_t* r, uint32_t addr) {
    asm volatile("ldmatrix.sync.aligned.m8n8.x2.trans.shared.b16 {%0,%1}, [%2];"
                 : "=r"(r[0]), "=r"(r[1]) : "r"(addr));
}
__device__ __forceinline__ void mma_bf16(float* c, const uint32_t* a, const uint32_t* b) {
    asm volatile(
        "mma.sync.aligned.m16n8k16.row.col.f32.bf16.bf16.f32 "
        "{%0,%1,%2,%3}, {%4,%5,%6,%7}, {%8,%9}, {%0,%1,%2,%3};"
        : "+f"(c[0]), "+f"(c[1]), "+f"(c[2]), "+f"(c[3])
        : "r"(a[0]), "r"(a[1]), "r"(a[2]), "r"(a[3]), "r"(b[0]), "r"(b[1]));
}
__device__ __forceinline__ void split_bf16(float x, __nv_bfloat16& h, __nv_bfloat16& l) {
    h = __float2bfloat16_rn(x);
    l = __float2bfloat16_rn(x - __bfloat162float(h));
}

// ---------------- tensor-core GEMM via mma.sync (bf16x3 split) ----------------
// out[M,128] = A[M,Kin] @ W[Kin,128] (+bias)(relu);  D = Ahi*Whi + Ahi*Wlo + Alo*Whi
#define PA 40
#define PB 136
__global__ void __launch_bounds__(256) tgemm(
    const float* __restrict__ A, const float* __restrict__ W,
    const float* __restrict__ bias, float* __restrict__ out,
    int M, int Kin, int doRelu) {
    __shared__ __align__(16) __nv_bfloat16 sAh[128 * PA];
    __shared__ __align__(16) __nv_bfloat16 sAl[128 * PA];
    __shared__ __align__(16) __nv_bfloat16 sBh[32 * PB];
    __shared__ __align__(16) __nv_bfloat16 sBl[32 * PB];
    int tid = threadIdx.x, wid = tid >> 5, lane = tid & 31;
    int bm = blockIdx.x * 128;
    int wm = wid & 3, wn = wid >> 2;   // warp tile: rows wm*32..+32, cols wn*64..+64

    float acc[2][8][4];
#pragma unroll
    for (int i = 0; i < 2; i++)
#pragma unroll
        for (int j = 0; j < 8; j++)
#pragma unroll
            for (int t = 0; t < 4; t++) acc[i][j][t] = 0.f;

    for (int kc = 0; kc < Kin; kc += 32) {
        // ---- A chunk: [128 rows x 32 k] fp32 -> hi/lo bf16 ----
#pragma unroll
        for (int i = 0; i < 4; i++) {
            int idx = tid + i * 256;        // 0..1023
            int row = idx >> 3;             // 0..127
            int c4 = idx & 7;               // float4 index along k
            int grow = bm + row;
            float4 v = make_float4(0.f, 0.f, 0.f, 0.f);
            if (grow < M) v = *(const float4*)(A + (size_t)grow * Kin + kc + (c4 << 2));
            __nv_bfloat16 h0, h1, h2, h3, l0, l1, l2, l3;
            split_bf16(v.x, h0, l0); split_bf16(v.y, h1, l1);
            split_bf16(v.z, h2, l2); split_bf16(v.w, h3, l3);
            __nv_bfloat162 hA = __halves2bfloat162(h0, h1), hB = __halves2bfloat162(h2, h3);
            __nv_bfloat162 lA = __halves2bfloat162(l0, l1), lB = __halves2bfloat162(l2, l3);
            int off = row * PA + (c4 << 2);
            *(uint2*)&sAh[off] = make_uint2(*(uint32_t*)&hA, *(uint32_t*)&hB);
            *(uint2*)&sAl[off] = make_uint2(*(uint32_t*)&lA, *(uint32_t*)&lB);
        }
        // ---- B chunk: [32 k x 128 n] fp32 -> hi/lo bf16 ----
#pragma unroll
        for (int i = 0; i < 4; i++) {
            int idx = tid + i * 256;        // 0..1023
            int row = idx >> 5;             // k row 0..31
            int c4 = idx & 31;              // float4 along n
            float4 v = *(const float4*)(W + (size_t)(kc + row) * 128 + (c4 << 2));
            __nv_bfloat16 h0, h1, h2, h3, l0, l1, l2, l3;
            split_bf16(v.x, h0, l0); split_bf16(v.y, h1, l1);
            split_bf16(v.z, h2, l2); split_bf16(v.w, h3, l3);
            __nv_bfloat162 hA = __halves2bfloat162(h0, h1), hB = __halves2bfloat162(h2, h3);
            __nv_bfloat162 lA = __halves2bfloat162(l0, l1), lB = __halves2bfloat162(l2, l3);
            int off = row * PB + (c4 << 2);
            *(uint2*)&sBh[off] = make_uint2(*(uint32_t*)&hA, *(uint32_t*)&hB);
            *(uint2*)&sBl[off] = make_uint2(*(uint32_t*)&lA, *(uint32_t*)&lB);
        }
        __syncthreads();

#pragma unroll
        for (int ks = 0; ks < 2; ks++) {
            int k0 = ks << 4;
            // A fragments for 2 m16 tiles (hi and lo)
            uint32_t ah[2][4], al[2][4];
            int t4 = lane >> 3, r8 = lane & 7;
            int arow_off = (t4 & 1) * 8 + r8;
            int acol_off = (t4 >> 1) * 8;
#pragma unroll
            for (int mt = 0; mt < 2; mt++) {
                int m0 = wm * 32 + mt * 16;
                int aoff = (m0 + arow_off) * PA + k0 + acol_off;
                ldsm_x4(ah[mt], (uint32_t)__cvta_generic_to_shared(&sAh[aoff]));
                ldsm_x4(al[mt], (uint32_t)__cvta_generic_to_shared(&sAl[aoff]));
            }
            int bt = (lane >> 3) & 1;
#pragma unroll
            for (int nt = 0; nt < 8; nt++) {
                int n0 = wn * 64 + nt * 8;
                int boff = (k0 + bt * 8 + r8) * PB + n0;
                uint32_t bh[2], bl[2];
                ldsm_x2t(bh, (uint32_t)__cvta_generic_to_shared(&sBh[boff]));
                ldsm_x2t(bl, (uint32_t)__cvta_generic_to_shared(&sBl[boff]));
#pragma unroll
                for (int mt = 0; mt < 2; mt++) {
                    mma_bf16(acc[mt][nt], ah[mt], bh);
                    mma_bf16(acc[mt][nt], ah[mt], bl);
                    mma_bf16(acc[mt][nt], al[mt], bh);
                }
            }
        }
        __syncthreads();
    }

    // ---- epilogue ----
    int grp = lane >> 2, qc = (lane & 3) << 1;
#pragma unroll
    for (int mt = 0; mt < 2; mt++) {
#pragma unroll
        for (int nt = 0; nt < 8; nt++) {
            int col = wn * 64 + nt * 8 + qc;
            float b0 = bias ? bias[col] : 0.f;
            float b1 = bias ? bias[col + 1] : 0.f;
#pragma unroll
            for (int hrow = 0; hrow < 2; hrow++) {
                int row = bm + wm * 32 + mt * 16 + grp + hrow * 8;
                if (row < M) {
                    float v0 = acc[mt][nt][hrow * 2 + 0] + b0;
                    float v1 = acc[mt][nt][hrow * 2 + 1] + b1;
                    if (doRelu) { v0 = fmaxf(v0, 0.f); v1 = fmaxf(v1, 0.f); }
                    *(float2*)(out + (size_t)row * 128 + col) = make_float2(v0, v1);
                }
            }
        }
    }
}

// ---------------- utility kernels ----------------
__global__ void fill0(float4* p, int n4) {
    for (int i = blockIdx.x * blockDim.x + threadIdx.x; i < n4; i += gridDim.x * blockDim.x)
        p[i] = make_float4(0.f, 0.f, 0.f, 0.f);
}
__global__ void filli0(int* p, int n) {
    for (int i = blockIdx.x * blockDim.x + threadIdx.x; i < n; i += gridDim.x * blockDim.x)
        p[i] = 0;
}

__global__ void degree_int(const int* __restrict__ src, const int* __restrict__ dst,
                           int* dout, int* din, int E) {
    int e = blockIdx.x * blockDim.x + threadIdx.x;
    if (e < E) {
        atomicAdd(&dout[src[e]], 1);
        atomicAdd(&din[dst[e]], 1);
    }
}

__global__ void make_norm(const int* __restrict__ d, float* __restrict__ out, int n) {
    int i = blockIdx.x * blockDim.x + threadIdx.x;
    if (i < n) out[i] = rsqrtf(fmaxf((float)d[i], 1.f));
}

__global__ void scan_rowptr(const int* __restrict__ cnt, int* __restrict__ rowptr, int n) {
    __shared__ int wsum[32];
    __shared__ int carry;
    int tid = threadIdx.x, lane = tid & 31, wid = tid >> 5;
    if (tid == 0) carry = 0;
    __syncthreads();
    for (int base = 0; base < n; base += 1024) {
        int v = (base + tid < n) ? cnt[base + tid] : 0;
        int inc = v;
#pragma unroll
        for (int off = 1; off < 32; off <<= 1) {
            int t = __shfl_up_sync(0xffffffffu, inc, off);
            if (lane >= off) inc += t;
        }
        if (lane == 31) wsum[wid] = inc;
        __syncthreads();
        if (wid == 0) {
            int s = wsum[lane];
            int si = s;
#pragma unroll
            for (int off = 1; off < 32; off <<= 1) {
                int t = __shfl_up_sync(0xffffffffu, si, off);
                if (lane >= off) si += t;
            }
            wsum[lane] = si - s;
        }
        __syncthreads();
        int excl = carry + wsum[wid] + inc - v;
        if (base + tid < n) rowptr[base + tid] = excl;
        __syncthreads();
        if (tid == 1023) carry = excl + v;
        __syncthreads();
    }
    if (threadIdx.x == 0) rowptr[n] = carry;
}

__global__ void build_eidx(const int* __restrict__ dst, const int* __restrict__ rowptr,
                           int* __restrict__ cursor, int* __restrict__ eidx, int E) {
    int e = blockIdx.x * blockDim.x + threadIdx.x;
    if (e < E) {
        int d = dst[e];
        int p = rowptr[d] + atomicAdd(&cursor[d], 1);
        eidx[p] = e;
    }
}

__global__ void build_wcat(const float* __restrict__ Wrel, const float* __restrict__ Wself,
                           float* __restrict__ Wcat) {
    int i = blockIdx.x * blockDim.x + threadIdx.x;
    if (i < RR * HH * HH) Wcat[i] = Wrel[i];
    else if (i < KCAT * HH) Wcat[i] = Wself[i - RR * HH * HH];
}

// ---------------- BatchNorm ----------------
__global__ void bn_stats(const float* __restrict__ X, int M, int K,
                         float* sum, float* sumsq) {
    int j = threadIdx.x;
    float s = 0.f, s2 = 0.f;
    for (int m = blockIdx.x; m < M; m += gridDim.x) {
        float v = X[(size_t)m * K + j];
        s += v; s2 += v * v;
    }
    atomicAdd(&sum[j], s);
    atomicAdd(&sumsq[j], s2);
}

__global__ void bn_fin(const float* sum, const float* sumsq, float invM, int K,
                       float* scale, float* shift) {
    int j = threadIdx.x;
    if (j < K) {
        float mean = sum[j] * invM;
        float var = sumsq[j] * invM - mean * mean;
        float sc = rsqrtf(var + EPSF);
        scale[j] = sc;
        shift[j] = BETAF - mean * sc;
    }
}

__global__ void bn_apply(const float* __restrict__ X, float* __restrict__ Y,
                         const float* __restrict__ scale, const float* __restrict__ shift,
                         const float* __restrict__ rowScale, int M, int K) {
    int total = M * (K >> 2);
    for (int i = blockIdx.x * blockDim.x + threadIdx.x; i < total; i += gridDim.x * blockDim.x) {
        int perRow = K >> 2;
        int row = i / perRow;
        int col = (i - row * perRow) << 2;
        float4 x = *(const float4*)(X + (size_t)row * K + col);
        float4 y;
        y.x = x.x * scale[col] + shift[col];
        y.y = x.y * scale[col + 1] + shift[col + 1];
        y.z = x.z * scale[col + 2] + shift[col + 2];
        y.w = x.w * scale[col + 3] + shift[col + 3];
        if (rowScale) {
            float s = rowScale[row];
            y.x *= s; y.y *= s; y.z *= s; y.w *= s;
        }
        *(float4*)(Y + (size_t)row * K + col) = y;
    }
}

__global__ void bn_small(const float* __restrict__ in, float* __restrict__ out, int M, int K) {
    int j = blockIdx.x * blockDim.x + threadIdx.x;
    if (j >= K) return;
    float s = 0.f, s2 = 0.f;
    for (int m = 0; m < M; m++) {
        float v = in[m * K + j];
        s += v; s2 += v * v;
    }
    float mean = s / M;
    float var = s2 / M - mean * mean;
    float r = rsqrtf(var + EPSF);
    for (int m = 0; m < M; m++)
        out[m * K + j] = (in[m * K + j] - mean) * r + BETAF;
}

// ---------------- CSR aggregation (warp per node, no atomics) ----------------
__global__ void csr_rel_gather(const float* __restrict__ B, const int* __restrict__ eidx,
                               const int* __restrict__ rowptr, const int* __restrict__ src,
                               const int* __restrict__ et, float* __restrict__ S, int Nn) {
    int gw = (blockIdx.x * blockDim.x + threadIdx.x) >> 5;
    if (gw >= Nn) return;
    int c = (threadIdx.x & 31) << 2;
    float4 a0 = make_float4(0, 0, 0, 0), a1 = a0, a2 = a0, a3 = a0, a4 = a0;
    int j0 = rowptr[gw], j1 = rowptr[gw + 1];
    for (int j = j0; j < j1; j++) {
        int e = eidx[j];
        int s = src[e];
        int r = et[e];
        float4 v = *(const float4*)(B + (size_t)s * HH + c);
        if (r == 0)      { a0.x += v.x; a0.y += v.y; a0.z += v.z; a0.w += v.w; }
        else if (r == 1) { a1.x += v.x; a1.y += v.y; a1.z += v.z; a1.w += v.w; }
        else if (r == 2) { a2.x += v.x; a2.y += v.y; a2.z += v.z; a2.w += v.w; }
        else if (r == 3) { a3.x += v.x; a3.y += v.y; a3.z += v.z; a3.w += v.w; }
        else             { a4.x += v.x; a4.y += v.y; a4.z += v.z; a4.w += v.w; }
    }
    float* Sp = S + (size_t)gw * KCAT + c;
    *(float4*)(Sp + 0)   = a0;
    *(float4*)(Sp + 128) = a1;
    *(float4*)(Sp + 256) = a2;
    *(float4*)(Sp + 384) = a3;
    *(float4*)(Sp + 512) = a4;
    *(float4*)(Sp + 640) = *(const float4*)(B + (size_t)gw * HH + c);
}

__global__ void csr_gather(const float* __restrict__ msg, const int* __restrict__ eidx,
                           const int* __restrict__ rowptr, const int* __restrict__ src,
                           const float* __restrict__ ew, int ewStride,
                           const float* __restrict__ outScale, float* __restrict__ out, int Nn) {
    int gw = (blockIdx.x * blockDim.x + threadIdx.x) >> 5;
    if (gw >= Nn) return;
    int c = (threadIdx.x & 31) << 2;
    float ax = 0.f, ay = 0.f, az = 0.f, aw = 0.f;
    int j0 = rowptr[gw], j1 = rowptr[gw + 1];
    for (int j = j0; j < j1; j++) {
        int e = eidx[j];
        int s = src[e];
        float w = ew ? ew[(size_t)e * ewStride] : 1.f;
        float4 v = *(const float4*)(msg + (size_t)s * HH + c);
        ax = fmaf(v.x, w, ax); ay = fmaf(v.y, w, ay);
        az = fmaf(v.z, w, az); aw = fmaf(v.w, w, aw);
    }
    float sc = outScale ? outScale[gw] : 1.f;
    float4 o = make_float4(ax * sc, ay * sc, az * sc, aw * sc);
    *(float4*)(out + (size_t)gw * HH + c) = o;
}

// ---------------- attention kernels ----------------
__global__ void node_att_kernel(const float* __restrict__ x, const float* __restrict__ W,
                                const float* __restrict__ b, float* __restrict__ natt, int Nn) {
    __shared__ float Ws[256];
    for (int i = threadIdx.x; i < 256; i += blockDim.x) Ws[i] = W[i];
    __syncthreads();
    int gi = blockIdx.x * blockDim.x + threadIdx.x;
    int n = gi >> 5, lane = threadIdx.x & 31;
    if (n >= Nn) return;
    float4 xv = *(const float4*)(x + (size_t)n * HH + (lane << 2));
    float vv[4] = {xv.x, xv.y, xv.z, xv.w};
    float s0 = 0.f, s1 = 0.f;
#pragma unroll
    for (int t = 0; t < 4; t++) {
        int k = (lane << 2) + t;
        s0 = fmaf(vv[t], Ws[k * 2 + 0], s0);
        s1 = fmaf(vv[t], Ws[k * 2 + 1], s1);
    }
    for (int o = 16; o > 0; o >>= 1) {
        s0 += __shfl_down_sync(0xffffffffu, s0, o);
        s1 += __shfl_down_sync(0xffffffffu, s1, o);
    }
    if (lane == 0) {
        float z0 = s0 + b[0], z1 = s1 + b[1];
        float m = fmaxf(z0, z1);
        float e0 = expf(z0 - m), e1 = expf(z1 - m);
        float inv = 1.f / (e0 + e1);
        natt[(size_t)n * 2 + 0] = e0 * inv;
        natt[(size_t)n * 2 + 1] = e1 * inv;
    }
}

__global__ void edge_att_kernel(const float* __restrict__ x, const int* __restrict__ src,
                                const int* __restrict__ dst, const float* __restrict__ W,
                                const float* __restrict__ b, float* __restrict__ eatt, int E) {
    __shared__ float Ws[512];
    for (int i = threadIdx.x; i < 512; i += blockDim.x) Ws[i] = W[i];
    __syncthreads();
    int gi = blockIdx.x * blockDim.x + threadIdx.x;
    int e = gi >> 5, lane = threadIdx.x & 31;
    if (e >= E) return;
    int s = src[e], d = dst[e];
    float4 xs = *(const float4*)(x + (size_t)s * HH + (lane << 2));
    float4 xd = *(const float4*)(x + (size_t)d * HH + (lane << 2));
    float vs[4] = {xs.x, xs.y, xs.z, xs.w};
    float vd[4] = {xd.x, xd.y, xd.z, xd.w};
    float s0 = 0.f, s1 = 0.f;
#pragma unroll
    for (int t = 0; t < 4; t++) {
        int k = (lane << 2) + t;
        s0 = fmaf(vs[t], Ws[k * 2 + 0], s0);
        s1 = fmaf(vs[t], Ws[k * 2 + 1], s1);
        s0 = fmaf(vd[t], Ws[(128 + k) * 2 + 0], s0);
        s1 = fmaf(vd[t], Ws[(128 + k) * 2 + 1], s1);
    }
    for (int o = 16; o > 0; o >>= 1) {
        s0 += __shfl_down_sync(0xffffffffu, s0, o);
        s1 += __shfl_down_sync(0xffffffffu, s1, o);
    }
    if (lane == 0) {
        float z0 = s0 + b[0], z1 = s1 + b[1];
        float m = fmaxf(z0, z1);
        float e0 = expf(z0 - m), e1 = expf(z1 - m);
        float inv = 1.f / (e0 + e1);
        eatt[(size_t)e * 2 + 0] = e0 * inv;
        eatt[(size_t)e * 2 + 1] = e1 * inv;
    }
}

__global__ void mul_att(const float* __restrict__ A, const float* __restrict__ natt,
                        int comp, float* __restrict__ B, int Nn) {
    int total = Nn * 32;
    for (int idx = blockIdx.x * blockDim.x + threadIdx.x; idx < total; idx += gridDim.x * blockDim.x) {
        int n = idx >> 5;
        int c = (idx & 31) << 2;
        float w = natt[(size_t)n * 2 + comp];
        float4 v = *(const float4*)(A + (size_t)n * HH + c);
        v.x *= w; v.y *= w; v.z *= w; v.w *= w;
        *(float4*)(B + (size_t)n * HH + c) = v;
    }
}

// ---------------- per-graph mean ----------------
__global__ void gcount_kernel(const int* __restrict__ gid, float* gcnt, int Nn) {
    int n = blockIdx.x * blockDim.x + threadIdx.x;
    if (n < Nn) atomicAdd(&gcnt[gid[n]], 1.f);
}

__global__ void graph_acc(const float* __restrict__ x, const int* __restrict__ gid,
                          float* __restrict__ gsum, int Nn) {
    int idx = blockIdx.x * blockDim.x + threadIdx.x;
    int n = idx >> 5;
    if (n >= Nn) return;
    int c = (idx & 31) << 2;
    int g = gid[n];
    float4 v = *(const float4*)(x + (size_t)n * HH + c);
    float* p = &gsum[g * HH + c];
    atomicAdd(p + 0, v.x); atomicAdd(p + 1, v.y);
    atomicAdd(p + 2, v.z); atomicAdd(p + 3, v.w);
}

__global__ void graph_div(const float* gsum, const float* gcnt, float* xg, float* outx, int total) {
    int i = blockIdx.x * blockDim.x + threadIdx.x;
    if (i >= total) return;
    int g = i / HH;
    float v = gsum[i] / fmaxf(gcnt[g], 1.f);
    xg[i] = v;
    outx[i] = v;
}

// ---------------- small FC / softmax heads ----------------
__global__ void fc_small(const float* __restrict__ A, const float* __restrict__ W,
                         const float* __restrict__ b, float* __restrict__ C,
                         int M, int Kin, int Kout, int doRelu) {
    int i = blockIdx.x * blockDim.x + threadIdx.x;
    if (i >= M * Kout) return;
    int m = i / Kout, j = i - m * Kout;
    float s = b ? b[j] : 0.f;
    for (int k = 0; k < Kin; k++) s = fmaf(A[m * Kin + k], W[k * Kout + j], s);
    C[i] = doRelu ? fmaxf(s, 0.f) : s;
}

__global__ void logsoftmax2(const float* Z, float* out, int M) {
    int i = blockIdx.x * blockDim.x + threadIdx.x;
    if (i >= M) return;
    float z0 = Z[i * 2], z1 = Z[i * 2 + 1];
    float m = fmaxf(z0, z1);
    float l = m + logf(expf(z0 - m) + expf(z1 - m));
    out[i * 2] = z0 - l;
    out[i * 2 + 1] = z1 - l;
}

// ---------------- threefry permutation (JAX partitionable semantics) ----------------
__device__ __forceinline__ void threefry2x32(uint32_t k0, uint32_t k1, uint32_t x0, uint32_t x1,
                                             uint32_t* o0, uint32_t* o1) {
    uint32_t ks[3] = {k0, k1, k0 ^ k1 ^ 0x1BD11BDAu};
    const int r1[4] = {13, 15, 26, 6};
    const int r2[4] = {17, 29, 16, 24};
    x0 += ks[0]; x1 += ks[1];
#pragma unroll
    for (int i = 0; i < 5; i++) {
        const int* rot = (i % 2 == 0) ? r1 : r2;
#pragma unroll
        for (int j = 0; j < 4; j++) {
            x0 += x1;
            x1 = (x1 << rot[j]) | (x1 >> (32 - rot[j]));
            x1 ^= x0;
        }
        x0 += ks[(i + 1) % 3];
        x1 += ks[(i + 2) % 3] + (uint32_t)(i + 1);
    }
    *o0 = x0; *o1 = x1;
}

__global__ void perm_kernel(int* perm) {
    __shared__ uint32_t keys[64];
    int t = threadIdx.x;
    uint32_t sk0, sk1;
    threefry2x32(0u, 42u, 0u, 1u, &sk0, &sk1);
    uint32_t o0, o1;
    threefry2x32(sk0, sk1, 0u, (uint32_t)t, &o0, &o1);
    keys[t] = o0 ^ o1;
    __syncthreads();
    uint32_t ki = keys[t];
    int rank = 0;
    for (int j = 0; j < 64; j++) {
        uint32_t kj = keys[j];
        rank += (kj < ki) || (kj == ki && j < t);
    }
    perm[rank] = t;
}

__global__ void xcat_kernel(const float* xcg, const float* xsg, const int* perm, float* xcat) {
    int i = blockIdx.x * blockDim.x + threadIdx.x;
    if (i >= GG * 256) return;
    int g = i >> 8, c = i & 255;
    xcat[i] = (c < HH) ? xcg[g * HH + c] : xsg[perm[g] * HH + (c - HH)];
}

// ---------------- launch ----------------
extern "C" void kernel_launch(void* const* d_in, const int* in_sizes, int n_in,
                              void* d_out, int out_size) {
    const float* feat = nullptr;
    const int *src = nullptr, *dst = nullptr, *et = nullptr, *gid = nullptr;
    const float* Wp[27];
    int wi = 0, eseen = 0;
    for (int i = 0; i < n_in; i++) {
        int sz = in_sizes[i];
        if (sz == NN * BERTD) feat = (const float*)d_in[i];
        else if (sz == EE) {
            if (eseen == 0) src = (const int*)d_in[i];
            else if (eseen == 1) dst = (const int*)d_in[i];
            else et = (const int*)d_in[i];
            eseen++;
        } else if (sz == NN) gid = (const int*)d_in[i];
        else if (wi < 27) Wp[wi++] = (const float*)d_in[i];
    }
    const float *W_red = Wp[0], *b_red = Wp[1], *W_rel = Wp[2], *W_self = Wp[3], *b_rel = Wp[4];
    const float *W_conv = Wp[5], *b_conv = Wp[6], *W_eatt = Wp[7], *b_eatt = Wp[8];
    const float *W_natt = Wp[9], *b_natt = Wp[10], *W_cconv = Wp[11], *b_cconv = Wp[12];
    const float *W_sconv = Wp[13], *b_sconv = Wp[14];
    const float *cfc1W = Wp[15], *cfc1b = Wp[16], *cfc2W = Wp[17], *cfc2b = Wp[18];
    const float *sfc1W = Wp[19], *sfc1b = Wp[20], *sfc2W = Wp[21], *sfc2b = Wp[22];
    const float *ccat1W = Wp[23], *ccat1b = Wp[24], *ccat2W = Wp[25], *ccat2b = Wp[26];

    float *A, *B, *Cc, *D, *S, *Wcat, *norms, *normd, *bsum, *bsq, *bsc, *bsh;
    float *gsum, *gcnt, *xcg, *xsg, *h1, *h2, *h3, *xcat;
    int *din, *dout, *rowptr, *cursor, *eidx, *perm;
    cudaGetSymbolAddress((void**)&A, g_A);
    cudaGetSymbolAddress((void**)&B, g_B);
    cudaGetSymbolAddress((void**)&Cc, g_Cacc);
    cudaGetSymbolAddress((void**)&D, g_D);
    cudaGetSymbolAddress((void**)&S, g_S);
    cudaGetSymbolAddress((void**)&Wcat, g_Wcat);
    cudaGetSymbolAddress((void**)&norms, g_norms);
    cudaGetSymbolAddress((void**)&normd, g_normd);
    cudaGetSymbolAddress((void**)&din, g_din);
    cudaGetSymbolAddress((void**)&dout, g_dout);
    cudaGetSymbolAddress((void**)&rowptr, g_rowptr);
    cudaGetSymbolAddress((void**)&cursor, g_cursor);
    cudaGetSymbolAddress((void**)&eidx, g_eidx);
    cudaGetSymbolAddress((void**)&bsum, g_sum);
    cudaGetSymbolAddress((void**)&bsq, g_sumsq);
    cudaGetSymbolAddress((void**)&bsc, g_scale);
    cudaGetSymbolAddress((void**)&bsh, g_shift);
    cudaGetSymbolAddress((void**)&gsum, g_gsum);
    cudaGetSymbolAddress((void**)&gcnt, g_gcnt);
    cudaGetSymbolAddress((void**)&xcg, g_xcg);
    cudaGetSymbolAddress((void**)&xsg, g_xsg);
    cudaGetSymbolAddress((void**)&h1, g_h1);
    cudaGetSymbolAddress((void**)&h2, g_h2);
    cudaGetSymbolAddress((void**)&h3, g_h3);
    cudaGetSymbolAddress((void**)&xcat, g_xcat);
    cudaGetSymbolAddress((void**)&perm, g_perm);

    float* out = (float*)d_out;
    float* out_causal = out;
    float* out_spur = out + GG * CCH;
    float* out_ctx = out + 2 * GG * CCH;
    float* out_xcg = out + 3 * GG * CCH;
    float* out_xsg = out_xcg + GG * HH;
    float* out_natt = out_xsg + GG * HH;
    float* out_eatt = out_natt + NN * 2;

    const int gemmGrid = (NN + 127) / 128;
    const int edgeWGrid = (EE * 32 + 255) / 256;
    const int nodeWGrid = (NN * 32 + 255) / 256;
    const int gatherGrid = (NN + 7) / 8;

    // ---- CSR build + degree norms ----
    filli0<<<64, 256>>>(din, NN);
    filli0<<<64, 256>>>(dout, NN);
    filli0<<<64, 256>>>(cursor, NN);
    degree_int<<<(EE + 255) / 256, 256>>>(src, dst, dout, din, EE);
    make_norm<<<(NN + 255) / 256, 256>>>(dout, norms, NN);
    make_norm<<<(NN + 255) / 256, 256>>>(din, normd, NN);
    scan_rowptr<<<1, 1024>>>(din, rowptr, NN);
    build_eidx<<<(EE + 255) / 256, 256>>>(dst, rowptr, cursor, eidx, EE);
    build_wcat<<<(KCAT * HH + 255) / 256, 256>>>(W_rel, W_self, Wcat);

    // ---- x = bn(feat @ W_red + b_red) ----
    tgemm<<<gemmGrid, 256>>>(feat, W_red, b_red, A, NN, BERTD, 0);
    fill0<<<1, 128>>>((float4*)bsum, 64);
    fill0<<<1, 128>>>((float4*)bsq, 64);
    bn_stats<<<512, 128>>>(A, NN, 128, bsum, bsq);
    bn_fin<<<1, 128>>>(bsum, bsq, 1.f / NN, 128, bsc, bsh);
    bn_apply<<<4096, 256>>>(A, B, bsc, bsh, nullptr, NN, 128);

    // ---- RelGraphConv (aggregate-first) ----
    csr_rel_gather<<<gatherGrid, 256>>>(B, eidx, rowptr, src, et, S, NN);
    tgemm<<<gemmGrid, 256>>>(S, Wcat, b_rel, A, NN, KCAT, 1);

    // ---- two GraphConv layers ----
    for (int i = 0; i < 2; i++) {
        fill0<<<1, 128>>>((float4*)bsum, 64);
        fill0<<<1, 128>>>((float4*)bsq, 64);
        bn_stats<<<512, 128>>>(A, NN, 128, bsum, bsq);
        bn_fin<<<1, 128>>>(bsum, bsq, 1.f / NN, 128, bsc, bsh);
        bn_apply<<<4096, 256>>>(A, B, bsc, bsh, norms, NN, 128);
        csr_gather<<<gatherGrid, 256>>>(B, eidx, rowptr, src, nullptr, 0, normd, Cc, NN);
        tgemm<<<gemmGrid, 256>>>(Cc, W_conv + (size_t)i * HH * HH, b_conv + i * HH, A, NN, HH, 1);
    }

    // ---- attentions ----
    node_att_kernel<<<nodeWGrid, 256>>>(A, W_natt, b_natt, out_natt, NN);
    edge_att_kernel<<<edgeWGrid, 256>>>(A, src, dst, W_eatt, b_eatt, out_eatt, EE);

    fill0<<<1, 16>>>((float4*)gcnt, GG / 4);
    gcount_kernel<<<(NN + 255) / 256, 256>>>(gid, gcnt, NN);

    // ---- causal branch ----
    mul_att<<<4096, 256>>>(A, out_natt, 0, B, NN);
    fill0<<<1, 128>>>((float4*)bsum, 64);
    fill0<<<1, 128>>>((float4*)bsq, 64);
    bn_stats<<<512, 128>>>(B, NN, 128, bsum, bsq);
    bn_fin<<<1, 128>>>(bsum, bsq, 1.f / NN, 128, bsc, bsh);
    bn_apply<<<4096, 256>>>(B, D, bsc, bsh, norms, NN, 128);
    csr_gather<<<gatherGrid, 256>>>(D, eidx, rowptr, src, out_eatt + 0, 2, normd, Cc, NN);
    tgemm<<<gemmGrid, 256>>>(Cc, W_cconv, b_cconv, D, NN, HH, 1);
    fill0<<<8, 256>>>((float4*)gsum, GG * HH / 4);
    graph_acc<<<nodeWGrid, 256>>>(D, gid, gsum, NN);
    graph_div<<<(GG * HH + 255) / 256, 256>>>(gsum, gcnt, xcg, out_xcg, GG * HH);

    // ---- spurious branch ----
    mul_att<<<4096, 256>>>(A, out_natt, 1, B, NN);
    fill0<<<1, 128>>>((float4*)bsum, 64);
    fill0<<<1, 128>>>((float4*)bsq, 64);
    bn_stats<<<512, 128>>>(B, NN, 128, bsum, bsq);
    bn_fin<<<1, 128>>>(bsum, bsq, 1.f / NN, 128, bsc, bsh);
    bn_apply<<<4096, 256>>>(B, D, bsc, bsh, norms, NN, 128);
    csr_gather<<<gatherGrid, 256>>>(D, eidx, rowptr, src, out_eatt + 1, 2, normd, Cc, NN);
    tgemm<<<gemmGrid, 256>>>(Cc, W_sconv, b_sconv, D, NN, HH, 1);
    fill0<<<8, 256>>>((float4*)gsum, GG * HH / 4);
    graph_acc<<<nodeWGrid, 256>>>(D, gid, gsum, NN);
    graph_div<<<(GG * HH + 255) / 256, 256>>>(gsum, gcnt, xsg, out_xsg, GG * HH);

    // ---- causal head ----
    bn_small<<<1, 128>>>(xcg, h1, GG, 128);
    fc_small<<<(GG * DD + 255) / 256, 256>>>(h1, cfc1W, cfc1b, h2, GG, 128, DD, 1);
    bn_small<<<1, 32>>>(h2, h3, GG, 32);
    fc_small<<<1, 256>>>(h3, cfc2W, cfc2b, out_causal, GG, DD, CCH, 0);

    // ---- spurious head ----
    bn_small<<<1, 128>>>(xsg, h1, GG, 128);
    fc_small<<<(GG * DD + 255) / 256, 256>>>(h1, sfc1W, sfc1b, h2, GG, 128, DD, 1);
    bn_small<<<1, 32>>>(h2, h3, GG, 32);
    fc_small<<<1, 256>>>(h3, sfc2W, sfc2b, h2, GG, DD, CCH, 0);
    logsoftmax2<<<1, 64>>>(h2, out_spur, GG);

    // ---- context head ----
    perm_kernel<<<1, 64>>>(perm);
    xcat_kernel<<<(GG * 256 + 255) / 256, 256>>>(xcg, xsg, perm, xcat);
    bn_small<<<1, 256>>>(xcat, h1, GG, 256);
    fc_small<<<(GG * DD + 255) / 256, 256>>>(h1, ccat1W, ccat1b, h2, GG, 256, DD, 1);
    bn_small<<<1, 32>>>(h2, h3, GG, 32);
    fc_small<<<1, 256>>>(h3, ccat2W, ccat2b, out_ctx, GG, DD, CCH, 0);
}

// round 8
// speedup vs baseline: 2.4007x; 1.0306x over previous
#include <cuda_runtime.h>
#include <cuda_bf16.h>
#include <math.h>
#include <stdint.h>

#define NN 50000
#define EE 800000
#define GG 64
#define RR 5
#define BERTD 768
#define HH 128
#define DD 32
#define CCH 2
#define EPSF 1e-5f
#define BETAF 1e-4f
#define KCAT 768   // 5*128 rel + 128 self

// ---------------- scratch (device globals; no allocation) ----------------
__device__ float g_A[NN * HH];
__device__ float g_B[NN * HH];
__device__ float g_Cacc[NN * HH];
__device__ float g_D[NN * HH];
__device__ float g_S[NN * KCAT];
__device__ float g_Wcat[KCAT * HH];
__device__ float g_norms[NN];
__device__ float g_normd[NN];
__device__ int g_din[NN];
__device__ int g_dout[NN];
__device__ int g_rowptr[NN + 1];
__device__ int g_cursor[NN];
__device__ int g_eidx[EE];
__device__ float g_sum[256];
__device__ float g_sumsq[256];
__device__ float g_scale[256];
__device__ float g_shift[256];
__device__ float g_gsum[GG * HH];
__device__ float g_gcnt[GG];
__device__ float g_xcg[GG * HH];
__device__ float g_xsg[GG * HH];
__device__ float g_h1[GG * 256];
__device__ float g_h2[GG * 256];
__device__ float g_h3[GG * 256];
__device__ float g_xcat[GG * 256];
__device__ int g_perm[GG];

// ---------------- mma.sync helpers ----------------
__device__ __forceinline__ void ldsm_x4(uint32_t* r, uint32_t addr) {
    asm volatile("ldmatrix.sync.aligned.m8n8.x4.shared.b16 {%0,%1,%2,%3}, [%4];"
                 : "=r"(r[0]), "=r"(r[1]), "=r"(r[2]), "=r"(r[3]) : "r"(addr));
}
__device__ __forceinline__ void ldsm_x2t(uint32_t* r, uint32_t addr) {
    asm volatile("ldmatrix.sync.aligned.m8n8.x2.trans.shared.b16 {%0,%1}, [%2];"
                 : "=r"(r[0]), "=r"(r[1]) : "r"(addr));
}
__device__ __forceinline__ void mma_bf16(float* c, const uint32_t* a, const uint32_t* b) {
    asm volatile(
        "mma.sync.aligned.m16n8k16.row.col.f32.bf16.bf16.f32 "
        "{%0,%1,%2,%3}, {%4,%5,%6,%7}, {%8,%9}, {%0,%1,%2,%3};"
        : "+f"(c[0]), "+f"(c[1]), "+f"(c[2]), "+f"(c[3])
        : "r"(a[0]), "r"(a[1]), "r"(a[2]), "r"(a[3]), "r"(b[0]), "r"(b[1]));
}
__device__ __forceinline__ void split_bf16(float x, __nv_bfloat16& h, __nv_bfloat16& l) {
    h = __float2bfloat16_rn(x);
    l = __float2bfloat16_rn(x - __bfloat162float(h));
}

// ---------------- tensor-core GEMM via mma.sync (bf16x3 split) ----------------
#define PA 40
#define PB 136
__global__ void __launch_bounds__(256) tgemm(
    const float* __restrict__ A, const float* __restrict__ W,
    const float* __restrict__ bias, float* __restrict__ out,
    int M, int Kin, int doRelu) {
    __shared__ __align__(16) __nv_bfloat16 sAh[128 * PA];
    __shared__ __align__(16) __nv_bfloat16 sAl[128 * PA];
    __shared__ __align__(16) __nv_bfloat16 sBh[32 * PB];
    __shared__ __align__(16) __nv_bfloat16 sBl[32 * PB];
    int tid = threadIdx.x, wid = tid >> 5, lane = tid & 31;
    int bm = blockIdx.x * 128;
    int wm = wid & 3, wn = wid >> 2;

    float acc[2][8][4];
#pragma unroll
    for (int i = 0; i < 2; i++)
#pragma unroll
        for (int j = 0; j < 8; j++)
#pragma unroll
            for (int t = 0; t < 4; t++) acc[i][j][t] = 0.f;

    for (int kc = 0; kc < Kin; kc += 32) {
#pragma unroll
        for (int i = 0; i < 4; i++) {
            int idx = tid + i * 256;
            int row = idx >> 3;
            int c4 = idx & 7;
            int grow = bm + row;
            float4 v = make_float4(0.f, 0.f, 0.f, 0.f);
            if (grow < M) v = *(const float4*)(A + (size_t)grow * Kin + kc + (c4 << 2));
            __nv_bfloat16 h0, h1, h2, h3, l0, l1, l2, l3;
            split_bf16(v.x, h0, l0); split_bf16(v.y, h1, l1);
            split_bf16(v.z, h2, l2); split_bf16(v.w, h3, l3);
            __nv_bfloat162 hA = __halves2bfloat162(h0, h1), hB = __halves2bfloat162(h2, h3);
            __nv_bfloat162 lA = __halves2bfloat162(l0, l1), lB = __halves2bfloat162(l2, l3);
            int off = row * PA + (c4 << 2);
            *(uint2*)&sAh[off] = make_uint2(*(uint32_t*)&hA, *(uint32_t*)&hB);
            *(uint2*)&sAl[off] = make_uint2(*(uint32_t*)&lA, *(uint32_t*)&lB);
        }
#pragma unroll
        for (int i = 0; i < 4; i++) {
            int idx = tid + i * 256;
            int row = idx >> 5;
            int c4 = idx & 31;
            float4 v = *(const float4*)(W + (size_t)(kc + row) * 128 + (c4 << 2));
            __nv_bfloat16 h0, h1, h2, h3, l0, l1, l2, l3;
            split_bf16(v.x, h0, l0); split_bf16(v.y, h1, l1);
            split_bf16(v.z, h2, l2); split_bf16(v.w, h3, l3);
            __nv_bfloat162 hA = __halves2bfloat162(h0, h1), hB = __halves2bfloat162(h2, h3);
            __nv_bfloat162 lA = __halves2bfloat162(l0, l1), lB = __halves2bfloat162(l2, l3);
            int off = row * PB + (c4 << 2);
            *(uint2*)&sBh[off] = make_uint2(*(uint32_t*)&hA, *(uint32_t*)&hB);
            *(uint2*)&sBl[off] = make_uint2(*(uint32_t*)&lA, *(uint32_t*)&lB);
        }
        __syncthreads();

#pragma unroll
        for (int ks = 0; ks < 2; ks++) {
            int k0 = ks << 4;
            uint32_t ah[2][4], al[2][4];
            int t4 = lane >> 3, r8 = lane & 7;
            int arow_off = (t4 & 1) * 8 + r8;
            int acol_off = (t4 >> 1) * 8;
#pragma unroll
            for (int mt = 0; mt < 2; mt++) {
                int m0 = wm * 32 + mt * 16;
                int aoff = (m0 + arow_off) * PA + k0 + acol_off;
                ldsm_x4(ah[mt], (uint32_t)__cvta_generic_to_shared(&sAh[aoff]));
                ldsm_x4(al[mt], (uint32_t)__cvta_generic_to_shared(&sAl[aoff]));
            }
            int bt = (lane >> 3) & 1;
#pragma unroll
            for (int nt = 0; nt < 8; nt++) {
                int n0 = wn * 64 + nt * 8;
                int boff = (k0 + bt * 8 + r8) * PB + n0;
                uint32_t bh[2], bl[2];
                ldsm_x2t(bh, (uint32_t)__cvta_generic_to_shared(&sBh[boff]));
                ldsm_x2t(bl, (uint32_t)__cvta_generic_to_shared(&sBl[boff]));
#pragma unroll
                for (int mt = 0; mt < 2; mt++) {
                    mma_bf16(acc[mt][nt], ah[mt], bh);
                    mma_bf16(acc[mt][nt], ah[mt], bl);
                    mma_bf16(acc[mt][nt], al[mt], bh);
                }
            }
        }
        __syncthreads();
    }

    int grp = lane >> 2, qc = (lane & 3) << 1;
#pragma unroll
    for (int mt = 0; mt < 2; mt++) {
#pragma unroll
        for (int nt = 0; nt < 8; nt++) {
            int col = wn * 64 + nt * 8 + qc;
            float b0 = bias ? bias[col] : 0.f;
            float b1 = bias ? bias[col + 1] : 0.f;
#pragma unroll
            for (int hrow = 0; hrow < 2; hrow++) {
                int row = bm + wm * 32 + mt * 16 + grp + hrow * 8;
                if (row < M) {
                    float v0 = acc[mt][nt][hrow * 2 + 0] + b0;
                    float v1 = acc[mt][nt][hrow * 2 + 1] + b1;
                    if (doRelu) { v0 = fmaxf(v0, 0.f); v1 = fmaxf(v1, 0.f); }
                    *(float2*)(out + (size_t)row * 128 + col) = make_float2(v0, v1);
                }
            }
        }
    }
}

// ---------------- utility kernels ----------------
__global__ void fill0(float4* p, int n4) {
    for (int i = blockIdx.x * blockDim.x + threadIdx.x; i < n4; i += gridDim.x * blockDim.x)
        p[i] = make_float4(0.f, 0.f, 0.f, 0.f);
}
__global__ void filli0(int* p, int n) {
    for (int i = blockIdx.x * blockDim.x + threadIdx.x; i < n; i += gridDim.x * blockDim.x)
        p[i] = 0;
}

__global__ void degree_int(const int* __restrict__ src, const int* __restrict__ dst,
                           int* dout, int* din, int E) {
    int e = blockIdx.x * blockDim.x + threadIdx.x;
    if (e < E) {
        atomicAdd(&dout[src[e]], 1);
        atomicAdd(&din[dst[e]], 1);
    }
}

__global__ void make_norm(const int* __restrict__ d, float* __restrict__ out, int n) {
    int i = blockIdx.x * blockDim.x + threadIdx.x;
    if (i < n) out[i] = rsqrtf(fmaxf((float)d[i], 1.f));
}

__global__ void scan_rowptr(const int* __restrict__ cnt, int* __restrict__ rowptr, int n) {
    __shared__ int wsum[32];
    __shared__ int carry;
    int tid = threadIdx.x, lane = tid & 31, wid = tid >> 5;
    if (tid == 0) carry = 0;
    __syncthreads();
    for (int base = 0; base < n; base += 1024) {
        int v = (base + tid < n) ? cnt[base + tid] : 0;
        int inc = v;
#pragma unroll
        for (int off = 1; off < 32; off <<= 1) {
            int t = __shfl_up_sync(0xffffffffu, inc, off);
            if (lane >= off) inc += t;
        }
        if (lane == 31) wsum[wid] = inc;
        __syncthreads();
        if (wid == 0) {
            int s = wsum[lane];
            int si = s;
#pragma unroll
            for (int off = 1; off < 32; off <<= 1) {
                int t = __shfl_up_sync(0xffffffffu, si, off);
                if (lane >= off) si += t;
            }
            wsum[lane] = si - s;
        }
        __syncthreads();
        int excl = carry + wsum[wid] + inc - v;
        if (base + tid < n) rowptr[base + tid] = excl;
        __syncthreads();
        if (tid == 1023) carry = excl + v;
        __syncthreads();
    }
    if (threadIdx.x == 0) rowptr[n] = carry;
}

__global__ void build_eidx(const int* __restrict__ dst, const int* __restrict__ rowptr,
                           int* __restrict__ cursor, int* __restrict__ eidx, int E) {
    int e = blockIdx.x * blockDim.x + threadIdx.x;
    if (e < E) {
        int d = dst[e];
        int p = rowptr[d] + atomicAdd(&cursor[d], 1);
        eidx[p] = e;
    }
}

__global__ void build_wcat(const float* __restrict__ Wrel, const float* __restrict__ Wself,
                           float* __restrict__ Wcat) {
    int i = blockIdx.x * blockDim.x + threadIdx.x;
    if (i < RR * HH * HH) Wcat[i] = Wrel[i];
    else if (i < KCAT * HH) Wcat[i] = Wself[i - RR * HH * HH];
}

// ---------------- BatchNorm stats ----------------
__global__ void bn_stats(const float* __restrict__ X, int M,
                         float* sum, float* sumsq) {
    int j = threadIdx.x;  // 128
    float s = 0.f, s2 = 0.f;
    for (int m = blockIdx.x; m < M; m += gridDim.x) {
        float v = X[(size_t)m * HH + j];
        s += v; s2 += v * v;
    }
    atomicAdd(&sum[j], s);
    atomicAdd(&sumsq[j], s2);
}

// stats of natt0*x and natt1*x simultaneously (slots [0:128] and [128:256])
__global__ void bn_stats2(const float* __restrict__ X, const float* __restrict__ natt,
                          int M, float* sum, float* sumsq) {
    int j = threadIdx.x;  // 128
    float s0 = 0.f, q0 = 0.f, s1 = 0.f, q1 = 0.f;
    for (int m = blockIdx.x; m < M; m += gridDim.x) {
        float x = X[(size_t)m * HH + j];
        float na0 = natt[2 * m], na1 = natt[2 * m + 1];
        float v0 = x * na0, v1 = x * na1;
        s0 += v0; q0 += v0 * v0;
        s1 += v1; q1 += v1 * v1;
    }
    atomicAdd(&sum[j], s0);       atomicAdd(&sumsq[j], q0);
    atomicAdd(&sum[128 + j], s1); atomicAdd(&sumsq[128 + j], q1);
}

__global__ void bn_fin(const float* sum, const float* sumsq, float invM, int K,
                       float* scale, float* shift) {
    int j = blockIdx.x * blockDim.x + threadIdx.x;
    if (j < K) {
        float mean = sum[j] * invM;
        float var = sumsq[j] * invM - mean * mean;
        float sc = rsqrtf(var + EPSF);
        scale[j] = sc;
        shift[j] = BETAF - mean * sc;
    }
}

__global__ void bn_small(const float* __restrict__ in, float* __restrict__ out, int M, int K) {
    int j = blockIdx.x * blockDim.x + threadIdx.x;
    if (j >= K) return;
    float s = 0.f, s2 = 0.f;
    for (int m = 0; m < M; m++) {
        float v = in[m * K + j];
        s += v; s2 += v * v;
    }
    float mean = s / M;
    float var = s2 / M - mean * mean;
    float r = rsqrtf(var + EPSF);
    for (int m = 0; m < M; m++)
        out[m * K + j] = (in[m * K + j] - mean) * r + BETAF;
}

// ---------------- fused CSR aggregation (BN applied inline; no atomics) ----------------
// RelGraphConv: S[:,r*128..] = sum_{e: et=r} bn(x)[src];  S[:,640..] = bn(x)[self]
__global__ void csr_rel_gather_bn(const float* __restrict__ X,
                                  const float* __restrict__ scale, const float* __restrict__ shift,
                                  const int* __restrict__ eidx, const int* __restrict__ rowptr,
                                  const int* __restrict__ src, const int* __restrict__ et,
                                  float* __restrict__ S, int Nn) {
    int gw = (blockIdx.x * blockDim.x + threadIdx.x) >> 5;
    if (gw >= Nn) return;
    int c = (threadIdx.x & 31) << 2;
    float4 sc = *(const float4*)(scale + c);
    float4 sh = *(const float4*)(shift + c);
    float4 a0 = make_float4(0, 0, 0, 0), a1 = a0, a2 = a0, a3 = a0, a4 = a0;
    int j0 = rowptr[gw], j1 = rowptr[gw + 1];
    for (int j = j0; j < j1; j++) {
        int e = eidx[j];
        int s = src[e];
        int r = et[e];
        float4 x = *(const float4*)(X + (size_t)s * HH + c);
        float4 v;
        v.x = fmaf(x.x, sc.x, sh.x); v.y = fmaf(x.y, sc.y, sh.y);
        v.z = fmaf(x.z, sc.z, sh.z); v.w = fmaf(x.w, sc.w, sh.w);
        if (r == 0)      { a0.x += v.x; a0.y += v.y; a0.z += v.z; a0.w += v.w; }
        else if (r == 1) { a1.x += v.x; a1.y += v.y; a1.z += v.z; a1.w += v.w; }
        else if (r == 2) { a2.x += v.x; a2.y += v.y; a2.z += v.z; a2.w += v.w; }
        else if (r == 3) { a3.x += v.x; a3.y += v.y; a3.z += v.z; a3.w += v.w; }
        else             { a4.x += v.x; a4.y += v.y; a4.z += v.z; a4.w += v.w; }
    }
    float4 xs = *(const float4*)(X + (size_t)gw * HH + c);
    float4 sv;
    sv.x = fmaf(xs.x, sc.x, sh.x); sv.y = fmaf(xs.y, sc.y, sh.y);
    sv.z = fmaf(xs.z, sc.z, sh.z); sv.w = fmaf(xs.w, sc.w, sh.w);
    float* Sp = S + (size_t)gw * KCAT + c;
    *(float4*)(Sp + 0)   = a0;
    *(float4*)(Sp + 128) = a1;
    *(float4*)(Sp + 256) = a2;
    *(float4*)(Sp + 384) = a3;
    *(float4*)(Sp + 512) = a4;
    *(float4*)(Sp + 640) = sv;
}

// GraphConv: out[d] = normd[d] * sum_e (bn(x)[src] * norms[src])
__global__ void csr_gather_bn(const float* __restrict__ X,
                              const float* __restrict__ scale, const float* __restrict__ shift,
                              const float* __restrict__ norms,
                              const int* __restrict__ eidx, const int* __restrict__ rowptr,
                              const int* __restrict__ src,
                              const float* __restrict__ normd, float* __restrict__ out, int Nn) {
    int gw = (blockIdx.x * blockDim.x + threadIdx.x) >> 5;
    if (gw >= Nn) return;
    int c = (threadIdx.x & 31) << 2;
    float4 sc = *(const float4*)(scale + c);
    float4 sh = *(const float4*)(shift + c);
    float ax = 0.f, ay = 0.f, az = 0.f, aw = 0.f;
    int j0 = rowptr[gw], j1 = rowptr[gw + 1];
    for (int j = j0; j < j1; j++) {
        int e = eidx[j];
        int s = src[e];
        float ns = norms[s];
        float4 x = *(const float4*)(X + (size_t)s * HH + c);
        ax += fmaf(x.x, sc.x, sh.x) * ns;
        ay += fmaf(x.y, sc.y, sh.y) * ns;
        az += fmaf(x.z, sc.z, sh.z) * ns;
        aw += fmaf(x.w, sc.w, sh.w) * ns;
    }
    float nd = normd[gw];
    *(float4*)(out + (size_t)gw * HH + c) = make_float4(ax * nd, ay * nd, az * nd, aw * nd);
}

// Both branches in ONE edge pass:
//   outc[d] = normd[d] * sum_e eatt0[e] * bn_c(natt0[s]*x[s]) * norms[s]
//   outs[d] = normd[d] * sum_e eatt1[e] * bn_s(natt1[s]*x[s]) * norms[s]
// scale/shift slots: causal [0:128], spurious [128:256]
__global__ void csr_gather_bn2(const float* __restrict__ X, const float* __restrict__ natt,
                               const float* __restrict__ scale, const float* __restrict__ shift,
                               const float* __restrict__ norms,
                               const int* __restrict__ eidx, const int* __restrict__ rowptr,
                               const int* __restrict__ src, const float* __restrict__ eatt,
                               const float* __restrict__ normd,
                               float* __restrict__ outc, float* __restrict__ outs, int Nn) {
    int gw = (blockIdx.x * blockDim.x + threadIdx.x) >> 5;
    if (gw >= Nn) return;
    int c = (threadIdx.x & 31) << 2;
    float4 sc0 = *(const float4*)(scale + c);
    float4 sh0 = *(const float4*)(shift + c);
    float4 sc1 = *(const float4*)(scale + 128 + c);
    float4 sh1 = *(const float4*)(shift + 128 + c);
    float cx = 0.f, cy = 0.f, cz = 0.f, cw = 0.f;
    float sx = 0.f, sy = 0.f, sz = 0.f, sw = 0.f;
    int j0 = rowptr[gw], j1 = rowptr[gw + 1];
    for (int j = j0; j < j1; j++) {
        int e = eidx[j];
        int s = src[e];
        float ns = norms[s];
        float na0 = natt[2 * s], na1 = natt[2 * s + 1];
        float w0 = eatt[2 * e], w1 = eatt[2 * e + 1];
        float4 x = *(const float4*)(X + (size_t)s * HH + c);
        float f0 = na0 * ns, f1 = na1 * ns;
        // v = ((x*na)*sc + sh) * ns * w = w * (x*(sc*f) + sh*ns)
        cx += w0 * fmaf(x.x, sc0.x * f0, sh0.x * ns);
        cy += w0 * fmaf(x.y, sc0.y * f0, sh0.y * ns);
        cz += w0 * fmaf(x.z, sc0.z * f0, sh0.z * ns);
        cw += w0 * fmaf(x.w, sc0.w * f0, sh0.w * ns);
        sx += w1 * fmaf(x.x, sc1.x * f1, sh1.x * ns);
        sy += w1 * fmaf(x.y, sc1.y * f1, sh1.y * ns);
        sz += w1 * fmaf(x.z, sc1.z * f1, sh1.z * ns);
        sw += w1 * fmaf(x.w, sc1.w * f1, sh1.w * ns);
    }
    float nd = normd[gw];
    *(float4*)(outc + (size_t)gw * HH + c) = make_float4(cx * nd, cy * nd, cz * nd, cw * nd);
    *(float4*)(outs + (size_t)gw * HH + c) = make_float4(sx * nd, sy * nd, sz * nd, sw * nd);
}

// ---------------- attention kernels ----------------
__global__ void node_att_kernel(const float* __restrict__ x, const float* __restrict__ W,
                                const float* __restrict__ b, float* __restrict__ natt, int Nn) {
    __shared__ float Ws[256];
    for (int i = threadIdx.x; i < 256; i += blockDim.x) Ws[i] = W[i];
    __syncthreads();
    int gi = blockIdx.x * blockDim.x + threadIdx.x;
    int n = gi >> 5, lane = threadIdx.x & 31;
    if (n >= Nn) return;
    float4 xv = *(const float4*)(x + (size_t)n * HH + (lane << 2));
    float vv[4] = {xv.x, xv.y, xv.z, xv.w};
    float s0 = 0.f, s1 = 0.f;
#pragma unroll
    for (int t = 0; t < 4; t++) {
        int k = (lane << 2) + t;
        s0 = fmaf(vv[t], Ws[k * 2 + 0], s0);
        s1 = fmaf(vv[t], Ws[k * 2 + 1], s1);
    }
    for (int o = 16; o > 0; o >>= 1) {
        s0 += __shfl_down_sync(0xffffffffu, s0, o);
        s1 += __shfl_down_sync(0xffffffffu, s1, o);
    }
    if (lane == 0) {
        float z0 = s0 + b[0], z1 = s1 + b[1];
        float m = fmaxf(z0, z1);
        float e0 = expf(z0 - m), e1 = expf(z1 - m);
        float inv = 1.f / (e0 + e1);
        natt[(size_t)n * 2 + 0] = e0 * inv;
        natt[(size_t)n * 2 + 1] = e1 * inv;
    }
}

__global__ void edge_att_kernel(const float* __restrict__ x, const int* __restrict__ src,
                                const int* __restrict__ dst, const float* __restrict__ W,
                                const float* __restrict__ b, float* __restrict__ eatt, int E) {
    __shared__ float Ws[512];
    for (int i = threadIdx.x; i < 512; i += blockDim.x) Ws[i] = W[i];
    __syncthreads();
    int gi = blockIdx.x * blockDim.x + threadIdx.x;
    int e = gi >> 5, lane = threadIdx.x & 31;
    if (e >= E) return;
    int s = src[e], d = dst[e];
    float4 xs = *(const float4*)(x + (size_t)s * HH + (lane << 2));
    float4 xd = *(const float4*)(x + (size_t)d * HH + (lane << 2));
    float vs[4] = {xs.x, xs.y, xs.z, xs.w};
    float vd[4] = {xd.x, xd.y, xd.z, xd.w};
    float s0 = 0.f, s1 = 0.f;
#pragma unroll
    for (int t = 0; t < 4; t++) {
        int k = (lane << 2) + t;
        s0 = fmaf(vs[t], Ws[k * 2 + 0], s0);
        s1 = fmaf(vs[t], Ws[k * 2 + 1], s1);
        s0 = fmaf(vd[t], Ws[(128 + k) * 2 + 0], s0);
        s1 = fmaf(vd[t], Ws[(128 + k) * 2 + 1], s1);
    }
    for (int o = 16; o > 0; o >>= 1) {
        s0 += __shfl_down_sync(0xffffffffu, s0, o);
        s1 += __shfl_down_sync(0xffffffffu, s1, o);
    }
    if (lane == 0) {
        float z0 = s0 + b[0], z1 = s1 + b[1];
        float m = fmaxf(z0, z1);
        float e0 = expf(z0 - m), e1 = expf(z1 - m);
        float inv = 1.f / (e0 + e1);
        eatt[(size_t)e * 2 + 0] = e0 * inv;
        eatt[(size_t)e * 2 + 1] = e1 * inv;
    }
}

// ---------------- per-graph mean ----------------
__global__ void gcount_kernel(const int* __restrict__ gid, float* gcnt, int Nn) {
    int n = blockIdx.x * blockDim.x + threadIdx.x;
    if (n < Nn) atomicAdd(&gcnt[gid[n]], 1.f);
}

__global__ void graph_acc(const float* __restrict__ x, const int* __restrict__ gid,
                          float* __restrict__ gsum, int Nn) {
    int idx = blockIdx.x * blockDim.x + threadIdx.x;
    int n = idx >> 5;
    if (n >= Nn) return;
    int c = (idx & 31) << 2;
    int g = gid[n];
    float4 v = *(const float4*)(x + (size_t)n * HH + c);
    float* p = &gsum[g * HH + c];
    atomicAdd(p + 0, v.x); atomicAdd(p + 1, v.y);
    atomicAdd(p + 2, v.z); atomicAdd(p + 3, v.w);
}

__global__ void graph_div(const float* gsum, const float* gcnt, float* xg, float* outx, int total) {
    int i = blockIdx.x * blockDim.x + threadIdx.x;
    if (i >= total) return;
    int g = i / HH;
    float v = gsum[i] / fmaxf(gcnt[g], 1.f);
    xg[i] = v;
    outx[i] = v;
}

// ---------------- small FC / softmax heads ----------------
__global__ void fc_small(const float* __restrict__ A, const float* __restrict__ W,
                         const float* __restrict__ b, float* __restrict__ C,
                         int M, int Kin, int Kout, int doRelu) {
    int i = blockIdx.x * blockDim.x + threadIdx.x;
    if (i >= M * Kout) return;
    int m = i / Kout, j = i - m * Kout;
    float s = b ? b[j] : 0.f;
    for (int k = 0; k < Kin; k++) s = fmaf(A[m * Kin + k], W[k * Kout + j], s);
    C[i] = doRelu ? fmaxf(s, 0.f) : s;
}

__global__ void logsoftmax2(const float* Z, float* out, int M) {
    int i = blockIdx.x * blockDim.x + threadIdx.x;
    if (i >= M) return;
    float z0 = Z[i * 2], z1 = Z[i * 2 + 1];
    float m = fmaxf(z0, z1);
    float l = m + logf(expf(z0 - m) + expf(z1 - m));
    out[i * 2] = z0 - l;
    out[i * 2 + 1] = z1 - l;
}

// ---------------- threefry permutation (JAX partitionable semantics) ----------------
__device__ __forceinline__ void threefry2x32(uint32_t k0, uint32_t k1, uint32_t x0, uint32_t x1,
                                             uint32_t* o0, uint32_t* o1) {
    uint32_t ks[3] = {k0, k1, k0 ^ k1 ^ 0x1BD11BDAu};
    const int r1[4] = {13, 15, 26, 6};
    const int r2[4] = {17, 29, 16, 24};
    x0 += ks[0]; x1 += ks[1];
#pragma unroll
    for (int i = 0; i < 5; i++) {
        const int* rot = (i % 2 == 0) ? r1 : r2;
#pragma unroll
        for (int j = 0; j < 4; j++) {
            x0 += x1;
            x1 = (x1 << rot[j]) | (x1 >> (32 - rot[j]));
            x1 ^= x0;
        }
        x0 += ks[(i + 1) % 3];
        x1 += ks[(i + 2) % 3] + (uint32_t)(i + 1);
    }
    *o0 = x0; *o1 = x1;
}

__global__ void perm_kernel(int* perm) {
    __shared__ uint32_t keys[64];
    int t = threadIdx.x;
    uint32_t sk0, sk1;
    threefry2x32(0u, 42u, 0u, 1u, &sk0, &sk1);
    uint32_t o0, o1;
    threefry2x32(sk0, sk1, 0u, (uint32_t)t, &o0, &o1);
    keys[t] = o0 ^ o1;
    __syncthreads();
    uint32_t ki = keys[t];
    int rank = 0;
    for (int j = 0; j < 64; j++) {
        uint32_t kj = keys[j];
        rank += (kj < ki) || (kj == ki && j < t);
    }
    perm[rank] = t;
}

__global__ void xcat_kernel(const float* xcg, const float* xsg, const int* perm, float* xcat) {
    int i = blockIdx.x * blockDim.x + threadIdx.x;
    if (i >= GG * 256) return;
    int g = i >> 8, c = i & 255;
    xcat[i] = (c < HH) ? xcg[g * HH + c] : xsg[perm[g] * HH + (c - HH)];
}

// ---------------- launch ----------------
extern "C" void kernel_launch(void* const* d_in, const int* in_sizes, int n_in,
                              void* d_out, int out_size) {
    const float* feat = nullptr;
    const int *src = nullptr, *dst = nullptr, *et = nullptr, *gid = nullptr;
    const float* Wp[27];
    int wi = 0, eseen = 0;
    for (int i = 0; i < n_in; i++) {
        int sz = in_sizes[i];
        if (sz == NN * BERTD) feat = (const float*)d_in[i];
        else if (sz == EE) {
            if (eseen == 0) src = (const int*)d_in[i];
            else if (eseen == 1) dst = (const int*)d_in[i];
            else et = (const int*)d_in[i];
            eseen++;
        } else if (sz == NN) gid = (const int*)d_in[i];
        else if (wi < 27) Wp[wi++] = (const float*)d_in[i];
    }
    const float *W_red = Wp[0], *b_red = Wp[1], *W_rel = Wp[2], *W_self = Wp[3], *b_rel = Wp[4];
    const float *W_conv = Wp[5], *b_conv = Wp[6], *W_eatt = Wp[7], *b_eatt = Wp[8];
    const float *W_natt = Wp[9], *b_natt = Wp[10], *W_cconv = Wp[11], *b_cconv = Wp[12];
    const float *W_sconv = Wp[13], *b_sconv = Wp[14];
    const float *cfc1W = Wp[15], *cfc1b = Wp[16], *cfc2W = Wp[17], *cfc2b = Wp[18];
    const float *sfc1W = Wp[19], *sfc1b = Wp[20], *sfc2W = Wp[21], *sfc2b = Wp[22];
    const float *ccat1W = Wp[23], *ccat1b = Wp[24], *ccat2W = Wp[25], *ccat2b = Wp[26];

    float *A, *B, *Cc, *D, *S, *Wcat, *norms, *normd, *bsum, *bsq, *bsc, *bsh;
    float *gsum, *gcnt, *xcg, *xsg, *h1, *h2, *h3, *xcat;
    int *din, *dout, *rowptr, *cursor, *eidx, *perm;
    cudaGetSymbolAddress((void**)&A, g_A);
    cudaGetSymbolAddress((void**)&B, g_B);
    cudaGetSymbolAddress((void**)&Cc, g_Cacc);
    cudaGetSymbolAddress((void**)&D, g_D);
    cudaGetSymbolAddress((void**)&S, g_S);
    cudaGetSymbolAddress((void**)&Wcat, g_Wcat);
    cudaGetSymbolAddress((void**)&norms, g_norms);
    cudaGetSymbolAddress((void**)&normd, g_normd);
    cudaGetSymbolAddress((void**)&din, g_din);
    cudaGetSymbolAddress((void**)&dout, g_dout);
    cudaGetSymbolAddress((void**)&rowptr, g_rowptr);
    cudaGetSymbolAddress((void**)&cursor, g_cursor);
    cudaGetSymbolAddress((void**)&eidx, g_eidx);
    cudaGetSymbolAddress((void**)&bsum, g_sum);
    cudaGetSymbolAddress((void**)&bsq, g_sumsq);
    cudaGetSymbolAddress((void**)&bsc, g_scale);
    cudaGetSymbolAddress((void**)&bsh, g_shift);
    cudaGetSymbolAddress((void**)&gsum, g_gsum);
    cudaGetSymbolAddress((void**)&gcnt, g_gcnt);
    cudaGetSymbolAddress((void**)&xcg, g_xcg);
    cudaGetSymbolAddress((void**)&xsg, g_xsg);
    cudaGetSymbolAddress((void**)&h1, g_h1);
    cudaGetSymbolAddress((void**)&h2, g_h2);
    cudaGetSymbolAddress((void**)&h3, g_h3);
    cudaGetSymbolAddress((void**)&xcat, g_xcat);
    cudaGetSymbolAddress((void**)&perm, g_perm);

    float* out = (float*)d_out;
    float* out_causal = out;
    float* out_spur = out + GG * CCH;
    float* out_ctx = out + 2 * GG * CCH;
    float* out_xcg = out + 3 * GG * CCH;
    float* out_xsg = out_xcg + GG * HH;
    float* out_natt = out_xsg + GG * HH;
    float* out_eatt = out_natt + NN * 2;

    const int gemmGrid = (NN + 127) / 128;
    const int edgeWGrid = (EE * 32 + 255) / 256;
    const int nodeWGrid = (NN * 32 + 255) / 256;
    const int gatherGrid = (NN + 7) / 8;

    // ---- CSR build + degree norms ----
    filli0<<<64, 256>>>(din, NN);
    filli0<<<64, 256>>>(dout, NN);
    filli0<<<64, 256>>>(cursor, NN);
    degree_int<<<(EE + 255) / 256, 256>>>(src, dst, dout, din, EE);
    make_norm<<<(NN + 255) / 256, 256>>>(dout, norms, NN);
    make_norm<<<(NN + 255) / 256, 256>>>(din, normd, NN);
    scan_rowptr<<<1, 1024>>>(din, rowptr, NN);
    build_eidx<<<(EE + 255) / 256, 256>>>(dst, rowptr, cursor, eidx, EE);
    build_wcat<<<(KCAT * HH + 255) / 256, 256>>>(W_rel, W_self, Wcat);

    // ---- x = bn(feat @ W_red + b_red)  (BN fused into rel-gather) ----
    tgemm<<<gemmGrid, 256>>>(feat, W_red, b_red, A, NN, BERTD, 0);
    fill0<<<1, 128>>>((float4*)bsum, 64);
    fill0<<<1, 128>>>((float4*)bsq, 64);
    bn_stats<<<512, 128>>>(A, NN, bsum, bsq);
    bn_fin<<<1, 128>>>(bsum, bsq, 1.f / NN, 128, bsc, bsh);

    // ---- RelGraphConv (aggregate-first, BN inline) ----
    csr_rel_gather_bn<<<gatherGrid, 256>>>(A, bsc, bsh, eidx, rowptr, src, et, S, NN);
    tgemm<<<gemmGrid, 256>>>(S, Wcat, b_rel, A, NN, KCAT, 1);

    // ---- two GraphConv layers (BN fused into gather) ----
    for (int i = 0; i < 2; i++) {
        fill0<<<1, 128>>>((float4*)bsum, 64);
        fill0<<<1, 128>>>((float4*)bsq, 64);
        bn_stats<<<512, 128>>>(A, NN, bsum, bsq);
        bn_fin<<<1, 128>>>(bsum, bsq, 1.f / NN, 128, bsc, bsh);
        csr_gather_bn<<<gatherGrid, 256>>>(A, bsc, bsh, norms, eidx, rowptr, src, normd, Cc, NN);
        tgemm<<<gemmGrid, 256>>>(Cc, W_conv + (size_t)i * HH * HH, b_conv + i * HH, A, NN, HH, 1);
    }

    // ---- attentions ----
    node_att_kernel<<<nodeWGrid, 256>>>(A, W_natt, b_natt, out_natt, NN);
    edge_att_kernel<<<edgeWGrid, 256>>>(A, src, dst, W_eatt, b_eatt, out_eatt, EE);

    fill0<<<1, 16>>>((float4*)gcnt, GG / 4);
    gcount_kernel<<<(NN + 255) / 256, 256>>>(gid, gcnt, NN);

    // ---- both branches: one stats pass + one fused gather pass ----
    fill0<<<1, 128>>>((float4*)bsum, 64);
    fill0<<<1, 128>>>((float4*)bsq, 64);
    bn_stats2<<<512, 128>>>(A, out_natt, NN, bsum, bsq);
    bn_fin<<<1, 256>>>(bsum, bsq, 1.f / NN, 256, bsc, bsh);
    csr_gather_bn2<<<gatherGrid, 256>>>(A, out_natt, bsc, bsh, norms, eidx, rowptr, src,
                                        out_eatt, normd, Cc, B, NN);

    // causal
    tgemm<<<gemmGrid, 256>>>(Cc, W_cconv, b_cconv, D, NN, HH, 1);
    fill0<<<8, 256>>>((float4*)gsum, GG * HH / 4);
    graph_acc<<<nodeWGrid, 256>>>(D, gid, gsum, NN);
    graph_div<<<(GG * HH + 255) / 256, 256>>>(gsum, gcnt, xcg, out_xcg, GG * HH);

    // spurious
    tgemm<<<gemmGrid, 256>>>(B, W_sconv, b_sconv, D, NN, HH, 1);
    fill0<<<8, 256>>>((float4*)gsum, GG * HH / 4);
    graph_acc<<<nodeWGrid, 256>>>(D, gid, gsum, NN);
    graph_div<<<(GG * HH + 255) / 256, 256>>>(gsum, gcnt, xsg, out_xsg, GG * HH);

    // ---- causal head ----
    bn_small<<<1, 128>>>(xcg, h1, GG, 128);
    fc_small<<<(GG * DD + 255) / 256, 256>>>(h1, cfc1W, cfc1b, h2, GG, 128, DD, 1);
    bn_small<<<1, 32>>>(h2, h3, GG, 32);
    fc_small<<<1, 256>>>(h3, cfc2W, cfc2b, out_causal, GG, DD, CCH, 0);

    // ---- spurious head ----
    bn_small<<<1, 128>>>(xsg, h1, GG, 128);
    fc_small<<<(GG * DD + 255) / 256, 256>>>(h1, sfc1W, sfc1b, h2, GG, 128, DD, 1);
    bn_small<<<1, 32>>>(h2, h3, GG, 32);
    fc_small<<<1, 256>>>(h3, sfc2W, sfc2b, h2, GG, DD, CCH, 0);
    logsoftmax2<<<1, 64>>>(h2, out_spur, GG);

    // ---- context head ----
    perm_kernel<<<1, 64>>>(perm);
    xcat_kernel<<<(GG * 256 + 255) / 256, 256>>>(xcg, xsg, perm, xcat);
    bn_small<<<1, 256>>>(xcat, h1, GG, 256);
    fc_small<<<(GG * DD + 255) / 256, 256>>>(h1, ccat1W, ccat1b, h2, GG, 256, DD, 1);
    bn_small<<<1, 32>>>(h2, h3, GG, 32);
    fc_small<<<1, 256>>>(h3, ccat2W, ccat2b, out_ctx, GG, DD, CCH, 0);
}